// round 1
// baseline (speedup 1.0000x reference)
#include <cuda_runtime.h>

// ---------------------------------------------------------------------------
// EntmaxAttention: B=8, N=1024, C=1024, H=8, D=128, alpha=1.5
// out   = [8,1024,1024]      -> d_out[0 .. 8388608)
// attn  = [8,8,1024,1024]    -> d_out[8388608 .. 75497472)
// ---------------------------------------------------------------------------

#define BDIM   8
#define HDIM   8
#define NDIM   1024
#define CDIM   1024
#define DDIM   128
#define OUT_ELEMS   (BDIM*NDIM*CDIM)          // 8388608
#define HEADS       (BDIM*HDIM)               // 64

// Scratch (alloc-free rule: __device__ globals)
__device__ float g_q[BDIM*HDIM*NDIM*DDIM];
__device__ float g_k[BDIM*HDIM*NDIM*DDIM];
__device__ float g_v[BDIM*HDIM*NDIM*DDIM];
__device__ float g_ctx[BDIM*NDIM*CDIM];

// ---------------------------------------------------------------------------
// SGEMM: C[M,N] = A[M,K] @ W[K,N] + bias   (128x128 tile, BK=16, 8x8/thread)
// OUT_MODE 0: Y[m*1024 + c]                      (final out projection)
// OUT_MODE 1: Y[((b*8+h)*1024 + n)*128 + d]      (QKV -> [B,H,N,D])
// M=8192, N=1024, K=1024 fixed.
// ---------------------------------------------------------------------------
template<int OUT_MODE>
__global__ void __launch_bounds__(256) gemm_xw_kernel(
    const float* __restrict__ A, const float* __restrict__ W,
    const float* __restrict__ bias, float* __restrict__ Y)
{
    const int K = 1024, N = 1024;
    __shared__ float As[16][132];
    __shared__ float Bs[16][132];

    int tid = threadIdx.x;
    int tx = tid & 15;          // N direction
    int ty = tid >> 4;          // M direction
    int row0 = blockIdx.y * 128;
    int col0 = blockIdx.x * 128;

    float acc[8][8];
    #pragma unroll
    for (int i = 0; i < 8; i++)
        #pragma unroll
        for (int j = 0; j < 8; j++) acc[i][j] = 0.f;

    for (int k0 = 0; k0 < K; k0 += 16) {
        // A tile: 128 rows x 16 k  (transposed scatter into As[k][m])
        #pragma unroll
        for (int it = 0; it < 2; it++) {
            int item = tid + it * 256;
            int r  = item >> 2;
            int kv = (item & 3) * 4;
            float4 v = *(const float4*)(A + (size_t)(row0 + r) * K + k0 + kv);
            As[kv+0][r] = v.x; As[kv+1][r] = v.y;
            As[kv+2][r] = v.z; As[kv+3][r] = v.w;
        }
        // W tile: 16 k x 128 n
        #pragma unroll
        for (int it = 0; it < 2; it++) {
            int item = tid + it * 256;
            int r  = item >> 5;
            int c4 = (item & 31) * 4;
            float4 v = *(const float4*)(W + (size_t)(k0 + r) * N + col0 + c4);
            *(float4*)&Bs[r][c4] = v;
        }
        __syncthreads();
        #pragma unroll
        for (int kk = 0; kk < 16; kk++) {
            float a[8], b[8];
            #pragma unroll
            for (int i = 0; i < 8; i++) a[i] = As[kk][ty*8 + i];
            #pragma unroll
            for (int j = 0; j < 8; j++) b[j] = Bs[kk][tx*8 + j];
            #pragma unroll
            for (int i = 0; i < 8; i++)
                #pragma unroll
                for (int j = 0; j < 8; j++)
                    acc[i][j] = fmaf(a[i], b[j], acc[i][j]);
        }
        __syncthreads();
    }

    #pragma unroll
    for (int i = 0; i < 8; i++) {
        int m = row0 + ty*8 + i;
        #pragma unroll
        for (int j = 0; j < 8; j++) {
            int c = col0 + tx*8 + j;
            float v = acc[i][j] + bias[c];
            if (OUT_MODE == 0) {
                Y[(size_t)m * 1024 + c] = v;
            } else {
                int b = m >> 10, n = m & 1023;
                int h = c >> 7,  d = c & 127;
                Y[((size_t)((b*8 + h) << 10) + n) * 128 + d] = v;
            }
        }
    }
}

// ---------------------------------------------------------------------------
// Scores: per head z, S[i,j] = scale * sum_d Q[z,i,d]*K[z,j,d]   (NT GEMM, K=128)
// grid (8, 8, 64)
// ---------------------------------------------------------------------------
__global__ void __launch_bounds__(256) scores_kernel(
    const float* __restrict__ Qb, const float* __restrict__ Kb,
    float* __restrict__ S)
{
    __shared__ float As[16][132];
    __shared__ float Bs[16][132];

    int tid = threadIdx.x;
    int tx = tid & 15;
    int ty = tid >> 4;
    int z = blockIdx.z;
    int row0 = blockIdx.y * 128;
    int col0 = blockIdx.x * 128;
    const float* Qh = Qb + (size_t)z * NDIM * DDIM;
    const float* Kh = Kb + (size_t)z * NDIM * DDIM;

    float acc[8][8];
    #pragma unroll
    for (int i = 0; i < 8; i++)
        #pragma unroll
        for (int j = 0; j < 8; j++) acc[i][j] = 0.f;

    for (int k0 = 0; k0 < DDIM; k0 += 16) {
        #pragma unroll
        for (int it = 0; it < 2; it++) {
            int item = tid + it * 256;
            int r  = item >> 2;
            int kv = (item & 3) * 4;
            float4 v = *(const float4*)(Qh + (size_t)(row0 + r) * DDIM + k0 + kv);
            As[kv+0][r] = v.x; As[kv+1][r] = v.y;
            As[kv+2][r] = v.z; As[kv+3][r] = v.w;
        }
        #pragma unroll
        for (int it = 0; it < 2; it++) {
            int item = tid + it * 256;
            int j  = item >> 2;
            int kv = (item & 3) * 4;
            float4 v = *(const float4*)(Kh + (size_t)(col0 + j) * DDIM + k0 + kv);
            Bs[kv+0][j] = v.x; Bs[kv+1][j] = v.y;
            Bs[kv+2][j] = v.z; Bs[kv+3][j] = v.w;
        }
        __syncthreads();
        #pragma unroll
        for (int kk = 0; kk < 16; kk++) {
            float a[8], b[8];
            #pragma unroll
            for (int i = 0; i < 8; i++) a[i] = As[kk][ty*8 + i];
            #pragma unroll
            for (int j = 0; j < 8; j++) b[j] = Bs[kk][tx*8 + j];
            #pragma unroll
            for (int i = 0; i < 8; i++)
                #pragma unroll
                for (int j = 0; j < 8; j++)
                    acc[i][j] = fmaf(a[i], b[j], acc[i][j]);
        }
        __syncthreads();
    }

    const float scale = 0.088388347648318440550f;   // 1/sqrt(128)
    float* Sh = S + (size_t)z * NDIM * NDIM;
    #pragma unroll
    for (int i = 0; i < 8; i++) {
        int m = row0 + ty*8 + i;
        #pragma unroll
        for (int j = 0; j < 8; j++) {
            int c = col0 + tx*8 + j;
            Sh[(size_t)m * NDIM + c] = acc[i][j] * scale;
        }
    }
}

// ---------------------------------------------------------------------------
// Entmax-1.5 bisection, in place. One warp per row of 1024. alpha=1.5 -> inv=2
// (pow is a square). dm0 halves each iter; after ~27 iters tau_lo+dm == tau_lo
// in fp32, so 34 iters == reference's 50 at fp32 precision.
// ---------------------------------------------------------------------------
__global__ void __launch_bounds__(256) entmax_kernel(float* __restrict__ attn)
{
    int gwarp = (blockIdx.x * blockDim.x + threadIdx.x) >> 5;
    int lane  = threadIdx.x & 31;
    float* row = attn + (size_t)gwarp * 1024;

    float xm[32];
    #pragma unroll
    for (int i = 0; i < 32; i++) xm[i] = 0.5f * row[i*32 + lane];

    // row max
    float mx = xm[0];
    #pragma unroll
    for (int i = 1; i < 32; i++) mx = fmaxf(mx, xm[i]);
    #pragma unroll
    for (int o = 16; o > 0; o >>= 1)
        mx = fmaxf(mx, __shfl_xor_sync(0xffffffffu, mx, o));

    float tau_lo = mx - 1.0f;
    float tau_hi = mx - 0.03125f;            // (1/1024)^0.5
    float dm = tau_hi - tau_lo;

    float s = 0.f;
    #pragma unroll
    for (int i = 0; i < 32; i++) {
        float t = fmaxf(xm[i] - tau_lo, 0.f);
        s = fmaf(t, t, s);
    }
    #pragma unroll
    for (int o = 16; o > 0; o >>= 1)
        s += __shfl_xor_sync(0xffffffffu, s, o);
    float f_lo = s - 1.0f;

    float tau_m = tau_lo;
    #pragma unroll 1
    for (int it = 0; it < 34; it++) {
        dm *= 0.5f;
        tau_m = tau_lo + dm;
        float fs = 0.f;
        #pragma unroll
        for (int i = 0; i < 32; i++) {
            float t = fmaxf(xm[i] - tau_m, 0.f);
            fs = fmaf(t, t, fs);
        }
        #pragma unroll
        for (int o = 16; o > 0; o >>= 1)
            fs += __shfl_xor_sync(0xffffffffu, fs, o);
        float f_m = fs - 1.0f;
        if (f_m * f_lo >= 0.f) tau_lo = tau_m;
    }

    float p[32];
    float psum = 0.f;
    #pragma unroll
    for (int i = 0; i < 32; i++) {
        float t = fmaxf(xm[i] - tau_m, 0.f);
        p[i] = t * t;
        psum += p[i];
    }
    #pragma unroll
    for (int o = 16; o > 0; o >>= 1)
        psum += __shfl_xor_sync(0xffffffffu, psum, o);
    float inv = 1.0f / psum;
    #pragma unroll
    for (int i = 0; i < 32; i++) row[i*32 + lane] = p[i] * inv;
}

// ---------------------------------------------------------------------------
// ctx = attn @ V per head: [1024,1024] x [1024,128] -> ctx[B,N,C] layout
// grid (1, 8, 64)
// ---------------------------------------------------------------------------
__global__ void __launch_bounds__(256) ctx_kernel(
    const float* __restrict__ attn, const float* __restrict__ Vb,
    float* __restrict__ ctx)
{
    __shared__ float As[16][132];
    __shared__ float Bs[16][132];

    int tid = threadIdx.x;
    int tx = tid & 15;
    int ty = tid >> 4;
    int z = blockIdx.z;
    int row0 = blockIdx.y * 128;
    const float* Ah = attn + (size_t)z * NDIM * NDIM;
    const float* Vh = Vb   + (size_t)z * NDIM * DDIM;

    float acc[8][8];
    #pragma unroll
    for (int i = 0; i < 8; i++)
        #pragma unroll
        for (int j = 0; j < 8; j++) acc[i][j] = 0.f;

    for (int k0 = 0; k0 < NDIM; k0 += 16) {
        #pragma unroll
        for (int it = 0; it < 2; it++) {
            int item = tid + it * 256;
            int r  = item >> 2;
            int kv = (item & 3) * 4;
            float4 v = *(const float4*)(Ah + (size_t)(row0 + r) * NDIM + k0 + kv);
            As[kv+0][r] = v.x; As[kv+1][r] = v.y;
            As[kv+2][r] = v.z; As[kv+3][r] = v.w;
        }
        // V tile: 16 k x 128 d  (full width)
        #pragma unroll
        for (int it = 0; it < 2; it++) {
            int item = tid + it * 256;
            int r  = item >> 5;
            int c4 = (item & 31) * 4;
            float4 v = *(const float4*)(Vh + (size_t)(k0 + r) * DDIM + c4);
            *(float4*)&Bs[r][c4] = v;
        }
        __syncthreads();
        #pragma unroll
        for (int kk = 0; kk < 16; kk++) {
            float a[8], b[8];
            #pragma unroll
            for (int i = 0; i < 8; i++) a[i] = As[kk][ty*8 + i];
            #pragma unroll
            for (int j = 0; j < 8; j++) b[j] = Bs[kk][tx*8 + j];
            #pragma unroll
            for (int i = 0; i < 8; i++)
                #pragma unroll
                for (int j = 0; j < 8; j++)
                    acc[i][j] = fmaf(a[i], b[j], acc[i][j]);
        }
        __syncthreads();
    }

    int bh = z >> 3, h = z & 7;
    #pragma unroll
    for (int i = 0; i < 8; i++) {
        int n = row0 + ty*8 + i;
        #pragma unroll
        for (int j = 0; j < 8; j++) {
            int d = tx*8 + j;
            ctx[((size_t)(bh*1024 + n)) * 1024 + h*128 + d] = acc[i][j];
        }
    }
}

// ---------------------------------------------------------------------------
extern "C" void kernel_launch(void* const* d_in, const int* in_sizes, int n_in,
                              void* d_out, int out_size)
{
    const float* x  = (const float*)d_in[0];
    const float* Wq = (const float*)d_in[1];
    const float* bq = (const float*)d_in[2];
    const float* Wk = (const float*)d_in[3];
    const float* bk = (const float*)d_in[4];
    const float* Wv = (const float*)d_in[5];
    const float* bv = (const float*)d_in[6];
    const float* Wo = (const float*)d_in[7];
    const float* bo = (const float*)d_in[8];

    float* out  = (float*)d_out;
    float* attn = out + OUT_ELEMS;

    float *qp, *kp, *vp, *cp;
    cudaGetSymbolAddress((void**)&qp, g_q);
    cudaGetSymbolAddress((void**)&kp, g_k);
    cudaGetSymbolAddress((void**)&vp, g_v);
    cudaGetSymbolAddress((void**)&cp, g_ctx);

    dim3 gProj(8, 64, 1);
    gemm_xw_kernel<1><<<gProj, 256>>>(x, Wq, bq, qp);
    gemm_xw_kernel<1><<<gProj, 256>>>(x, Wk, bk, kp);
    gemm_xw_kernel<1><<<gProj, 256>>>(x, Wv, bv, vp);

    scores_kernel<<<dim3(8, 8, HEADS), 256>>>(qp, kp, attn);

    entmax_kernel<<<8192, 256>>>(attn);

    ctx_kernel<<<dim3(1, 8, HEADS), 256>>>(attn, vp, cp);

    gemm_xw_kernel<0><<<gProj, 256>>>(cp, Wo, bo, out);
}

// round 3
// speedup vs baseline: 2.0210x; 2.0210x over previous
#include <cuda_runtime.h>
#include <cuda_bf16.h>
#include <cstdint>

// ===========================================================================
// EntmaxAttention B=8, N=1024, C=1024, H=8, D=128, alpha=1.5
// out  = [8,1024,1024]   -> d_out[0..8388608)
// attn = [8,8,1024,1024] -> d_out[8388608..75497472)
//
// Base sm_103 target (no 'a' features): GEMMs via mma.sync m16n8k16 bf16
// (HMMA), fp32 accum, 2-way bf16 split operands with 3-product compensation.
// cp.async double-buffered smem, 128x128 tiles, BK=32.
// ===========================================================================

#define BDIM 8
#define HDIM 8
#define NDIM 1024
#define CDIM 1024
#define DDIM 128
#define OUT_ELEMS (BDIM*NDIM*CDIM)
#define HEADS (BDIM*HDIM)

// smem geometry (bytes)
#define SAB 40                    // padded row stride in bf16 elements (80B)
#define TILE_BYTES 10240          // 128 rows * 80B
#define STAGE_BYTES 40960         // Ah | Al | Bh | Bl
#define SMEM_TOTAL (2*STAGE_BYTES)

__device__ __forceinline__ uint32_t smem_u32(const void* p) {
    uint32_t a;
    asm("{ .reg .u64 t; cvta.to.shared.u64 t, %1; cvt.u32.u64 %0, t; }"
        : "=r"(a) : "l"(p));
    return a;
}
__device__ __forceinline__ void cpa16(uint32_t dst, const void* src) {
    asm volatile("cp.async.cg.shared.global [%0], [%1], 16;" :: "r"(dst), "l"(src));
}
__device__ __forceinline__ void cpa_commit() {
    asm volatile("cp.async.commit_group;" ::: "memory");
}
template<int N>
__device__ __forceinline__ void cpa_wait() {
    asm volatile("cp.async.wait_group %0;" :: "n"(N) : "memory");
}
__device__ __forceinline__ void mma16816(float* d, const uint32_t* a, const uint32_t* b) {
    asm volatile("mma.sync.aligned.m16n8k16.row.col.f32.bf16.bf16.f32 "
        "{%0,%1,%2,%3}, {%4,%5,%6,%7}, {%8,%9}, {%0,%1,%2,%3};"
        : "+f"(d[0]), "+f"(d[1]), "+f"(d[2]), "+f"(d[3])
        : "r"(a[0]), "r"(a[1]), "r"(a[2]), "r"(a[3]), "r"(b[0]), "r"(b[1]));
}

// ------------------------- scratch (device globals) ------------------------
__device__ __nv_bfloat16 g_xh[OUT_ELEMS],  g_xl[OUT_ELEMS];
__device__ __nv_bfloat16 g_wqh[CDIM*CDIM], g_wql[CDIM*CDIM];
__device__ __nv_bfloat16 g_wkh[CDIM*CDIM], g_wkl[CDIM*CDIM];
__device__ __nv_bfloat16 g_wvh[CDIM*CDIM], g_wvl[CDIM*CDIM];
__device__ __nv_bfloat16 g_woh[CDIM*CDIM], g_wol[CDIM*CDIM];
__device__ __nv_bfloat16 g_qh[OUT_ELEMS],  g_ql[OUT_ELEMS];   // [BH,N,D]
__device__ __nv_bfloat16 g_kh[OUT_ELEMS],  g_kl[OUT_ELEMS];   // [BH,N,D]
__device__ __nv_bfloat16 g_vth[OUT_ELEMS], g_vtl[OUT_ELEMS];  // [BH,D,N]
__device__ __nv_bfloat16 g_ah[(size_t)HEADS*NDIM*NDIM], g_al[(size_t)HEADS*NDIM*NDIM];
__device__ __nv_bfloat16 g_ch[OUT_ELEMS],  g_cl[OUT_ELEMS];   // ctx [B,N,C]

// ------------------------- split kernels ------------------------------------
__global__ void __launch_bounds__(256) split_kernel(
    const float* __restrict__ src, __nv_bfloat16* __restrict__ hi,
    __nv_bfloat16* __restrict__ lo, int n)
{
    int i = blockIdx.x * 256 + threadIdx.x;
    if (i < n) {
        float v = src[i];
        __nv_bfloat16 h = __float2bfloat16(v);
        hi[i] = h;
        lo[i] = __float2bfloat16(v - __bfloat162float(h));
    }
}

// W [k,n] row-major -> WT hi/lo [n,k]
__global__ void __launch_bounds__(1024) splitT_kernel(
    const float* __restrict__ W, __nv_bfloat16* __restrict__ hiT,
    __nv_bfloat16* __restrict__ loT)
{
    __shared__ float t[32][33];
    int bx = blockIdx.x * 32, by = blockIdx.y * 32;
    int x = threadIdx.x, y = threadIdx.y;
    t[y][x] = W[(size_t)(by + y) * CDIM + bx + x];
    __syncthreads();
    float v = t[x][y];   // = W[by+x][bx+y]
    __nv_bfloat16 h = __float2bfloat16(v);
    size_t o = (size_t)(bx + y) * CDIM + by + x;
    hiT[o] = h;
    loT[o] = __float2bfloat16(v - __bfloat162float(h));
}

// ------------------------- generic HMMA GEMM --------------------------------
// D[m,n] = sum_k A[m,k]*B[n,k]  (both operands K-major), 128x128 tile, BK=32.
// MODE 0: QK proj  -> hi/lo at [B,H,N,D]          (+bias)
// MODE 1: V proj   -> hi/lo at vT [B,H,D,N]       (+bias)
// MODE 2: scores   -> fp32*scale at outF[z<<20]
// MODE 3: ctx      -> hi/lo at ctx [B,N,C]
// MODE 4: out proj -> fp32+bias at outF
struct GP {
    const __nv_bfloat16 *Ah, *Al, *Bh, *Bl;
    long long strideAz, strideBz;
    int lda, ldb, K;
    const float* bias;
    float scale;
    float* outF;
    __nv_bfloat16 *outH, *outL;
};

template<int MODE>
__global__ void __launch_bounds__(256) gemm_hmma(GP p)
{
    extern __shared__ char smem[];
    const uint32_t sbase = smem_u32(smem);
    const int tid = threadIdx.x;
    const int wid = tid >> 5;
    const int lane = tid & 31;
    const int g = lane >> 2;       // groupID 0..7
    const int tq = lane & 3;       // 0..3
    const int warp_m = (wid >> 2) * 64;   // 0 / 64
    const int warp_n = (wid & 3) * 32;    // 0..96
    const int z = blockIdx.z;
    const int row0 = blockIdx.y * 128;
    const int col0 = blockIdx.x * 128;

    const __nv_bfloat16* Ah = p.Ah + (size_t)z * p.strideAz;
    const __nv_bfloat16* Al = p.Al + (size_t)z * p.strideAz;
    const __nv_bfloat16* Bh = p.Bh + (size_t)z * p.strideBz;
    const __nv_bfloat16* Bl = p.Bl + (size_t)z * p.strideBz;

    float acc[4][4][4];
    #pragma unroll
    for (int i = 0; i < 4; i++)
        #pragma unroll
        for (int j = 0; j < 4; j++)
            #pragma unroll
            for (int e = 0; e < 4; e++) acc[i][j][e] = 0.f;

    const int nchunk = p.K >> 5;

    // --- prefetch helper (issued inline) ---
    // thread t handles rows id>>2, 16B chunk id&3, for id = t and t+256
    auto prefetch = [&](int c) {
        int s = c & 1;
        int k0 = c << 5;
        uint32_t sb = sbase + s * STAGE_BYTES;
        #pragma unroll
        for (int it = 0; it < 2; it++) {
            int id = tid + it * 256;
            int r = id >> 2;
            int ch = id & 3;
            uint32_t doff = (uint32_t)(r * 80 + ch * 16);
            size_t ga = (size_t)(row0 + r) * p.lda + k0 + ch * 8;
            size_t gb = (size_t)(col0 + r) * p.ldb + k0 + ch * 8;
            cpa16(sb + doff,                   Ah + ga);
            cpa16(sb + TILE_BYTES + doff,      Al + ga);
            cpa16(sb + 2*TILE_BYTES + doff,    Bh + gb);
            cpa16(sb + 3*TILE_BYTES + doff,    Bl + gb);
        }
        cpa_commit();
    };

    prefetch(0);

    for (int c = 0; c < nchunk; c++) {
        if (c + 1 < nchunk) { prefetch(c + 1); cpa_wait<1>(); }
        else                { cpa_wait<0>(); }
        __syncthreads();

        int s = c & 1;
        const __nv_bfloat16* Ahs = (const __nv_bfloat16*)(smem + s*STAGE_BYTES);
        const __nv_bfloat16* Als = (const __nv_bfloat16*)(smem + s*STAGE_BYTES + TILE_BYTES);
        const __nv_bfloat16* Bhs = (const __nv_bfloat16*)(smem + s*STAGE_BYTES + 2*TILE_BYTES);
        const __nv_bfloat16* Bls = (const __nv_bfloat16*)(smem + s*STAGE_BYTES + 3*TILE_BYTES);

        #pragma unroll
        for (int s16 = 0; s16 < 2; s16++) {
            const int kb = s16 * 16 + tq * 2;
            uint32_t bh[4][2], bl[4][2];
            #pragma unroll
            for (int j = 0; j < 4; j++) {
                int nl = warp_n + j * 8 + g;
                bh[j][0] = *(const uint32_t*)(Bhs + nl*SAB + kb);
                bh[j][1] = *(const uint32_t*)(Bhs + nl*SAB + kb + 8);
                bl[j][0] = *(const uint32_t*)(Bls + nl*SAB + kb);
                bl[j][1] = *(const uint32_t*)(Bls + nl*SAB + kb + 8);
            }
            uint32_t ah[4][4], al[4][4];
            #pragma unroll
            for (int i = 0; i < 4; i++) {
                int ml = warp_m + i * 16 + g;
                int base = ml*SAB + kb;
                ah[i][0] = *(const uint32_t*)(Ahs + base);
                ah[i][1] = *(const uint32_t*)(Ahs + base + 8*SAB);
                ah[i][2] = *(const uint32_t*)(Ahs + base + 8);
                ah[i][3] = *(const uint32_t*)(Ahs + base + 8*SAB + 8);
                al[i][0] = *(const uint32_t*)(Als + base);
                al[i][1] = *(const uint32_t*)(Als + base + 8*SAB);
                al[i][2] = *(const uint32_t*)(Als + base + 8);
                al[i][3] = *(const uint32_t*)(Als + base + 8*SAB + 8);
            }
            #pragma unroll
            for (int i = 0; i < 4; i++)
                #pragma unroll
                for (int j = 0; j < 4; j++) {
                    mma16816(acc[i][j], ah[i], bh[j]);
                    mma16816(acc[i][j], ah[i], bl[j]);
                    mma16816(acc[i][j], al[i], bh[j]);
                }
        }
        __syncthreads();
    }

    // --- epilogue ---
    #pragma unroll
    for (int i = 0; i < 4; i++) {
        #pragma unroll
        for (int j = 0; j < 4; j++) {
            #pragma unroll
            for (int e = 0; e < 4; e++) {
                int m  = row0 + warp_m + i*16 + g + ((e >> 1) ? 8 : 0);
                int cc = col0 + warp_n + j*8 + tq*2 + (e & 1);
                float val = acc[i][j][e];
                if (MODE == 0) {
                    float v = val + p.bias[cc];
                    int b = m >> 10, nn = m & 1023;
                    int h = cc >> 7, d = cc & 127;
                    size_t o = ((size_t)(((b*8 + h) << 10) + nn)) * 128 + d;
                    __nv_bfloat16 hh = __float2bfloat16(v);
                    p.outH[o] = hh;
                    p.outL[o] = __float2bfloat16(v - __bfloat162float(hh));
                } else if (MODE == 1) {
                    float v = val + p.bias[cc];
                    int b = m >> 10, nn = m & 1023;
                    int h = cc >> 7, d = cc & 127;
                    size_t o = ((size_t)(((b*8 + h) << 7) + d)) * 1024 + nn;
                    __nv_bfloat16 hh = __float2bfloat16(v);
                    p.outH[o] = hh;
                    p.outL[o] = __float2bfloat16(v - __bfloat162float(hh));
                } else if (MODE == 2) {
                    p.outF[((size_t)z << 20) + (size_t)m * 1024 + cc] = val * p.scale;
                } else if (MODE == 3) {
                    int b = z >> 3, h = z & 7;
                    size_t o = ((size_t)((b << 10) + m)) * 1024 + h * 128 + cc;
                    __nv_bfloat16 hh = __float2bfloat16(val);
                    p.outH[o] = hh;
                    p.outL[o] = __float2bfloat16(val - __bfloat162float(hh));
                } else {
                    p.outF[(size_t)m * 1024 + cc] = val + p.bias[cc];
                }
            }
        }
    }
}

// ------------------------- entmax (in place, + bf16 splits) ----------------
__global__ void __launch_bounds__(256) entmax_kernel(
    float* __restrict__ attn, __nv_bfloat16* __restrict__ ah,
    __nv_bfloat16* __restrict__ al)
{
    int gwarp = (blockIdx.x * blockDim.x + threadIdx.x) >> 5;
    int lane  = threadIdx.x & 31;
    size_t rbase = (size_t)gwarp * 1024;
    float* row = attn + rbase;

    float xm[32];
    #pragma unroll
    for (int i = 0; i < 32; i++) xm[i] = 0.5f * row[i*32 + lane];

    float mx = xm[0];
    #pragma unroll
    for (int i = 1; i < 32; i++) mx = fmaxf(mx, xm[i]);
    #pragma unroll
    for (int o = 16; o > 0; o >>= 1)
        mx = fmaxf(mx, __shfl_xor_sync(0xffffffffu, mx, o));

    float tau_lo = mx - 1.0f;
    float dm = 1.0f - 0.03125f;

    float s = 0.f;
    #pragma unroll
    for (int i = 0; i < 32; i++) {
        float t = fmaxf(xm[i] - tau_lo, 0.f);
        s = fmaf(t, t, s);
    }
    #pragma unroll
    for (int o = 16; o > 0; o >>= 1)
        s += __shfl_xor_sync(0xffffffffu, s, o);
    float f_lo = s - 1.0f;

    float tau_m = tau_lo;
    #pragma unroll 1
    for (int it = 0; it < 34; it++) {
        dm *= 0.5f;
        tau_m = tau_lo + dm;
        float fs = 0.f;
        #pragma unroll
        for (int i = 0; i < 32; i++) {
            float t = fmaxf(xm[i] - tau_m, 0.f);
            fs = fmaf(t, t, fs);
        }
        #pragma unroll
        for (int o = 16; o > 0; o >>= 1)
            fs += __shfl_xor_sync(0xffffffffu, fs, o);
        if ((fs - 1.0f) * f_lo >= 0.f) tau_lo = tau_m;
    }

    float pv[32];
    float psum = 0.f;
    #pragma unroll
    for (int i = 0; i < 32; i++) {
        float t = fmaxf(xm[i] - tau_m, 0.f);
        pv[i] = t * t;
        psum += pv[i];
    }
    #pragma unroll
    for (int o = 16; o > 0; o >>= 1)
        psum += __shfl_xor_sync(0xffffffffu, psum, o);
    float inv = 1.0f / psum;
    #pragma unroll
    for (int i = 0; i < 32; i++) {
        float v = pv[i] * inv;
        int idx = i*32 + lane;
        row[idx] = v;
        __nv_bfloat16 hh = __float2bfloat16(v);
        ah[rbase + idx] = hh;
        al[rbase + idx] = __float2bfloat16(v - __bfloat162float(hh));
    }
}

// ---------------------------------------------------------------------------
extern "C" void kernel_launch(void* const* d_in, const int* in_sizes, int n_in,
                              void* d_out, int out_size)
{
    const float* x  = (const float*)d_in[0];
    const float* Wq = (const float*)d_in[1];
    const float* bq = (const float*)d_in[2];
    const float* Wk = (const float*)d_in[3];
    const float* bk = (const float*)d_in[4];
    const float* Wv = (const float*)d_in[5];
    const float* bv = (const float*)d_in[6];
    const float* Wo = (const float*)d_in[7];
    const float* bo = (const float*)d_in[8];

    float* out  = (float*)d_out;
    float* attn = out + OUT_ELEMS;

    cudaFuncSetAttribute(gemm_hmma<0>, cudaFuncAttributeMaxDynamicSharedMemorySize, SMEM_TOTAL);
    cudaFuncSetAttribute(gemm_hmma<1>, cudaFuncAttributeMaxDynamicSharedMemorySize, SMEM_TOTAL);
    cudaFuncSetAttribute(gemm_hmma<2>, cudaFuncAttributeMaxDynamicSharedMemorySize, SMEM_TOTAL);
    cudaFuncSetAttribute(gemm_hmma<3>, cudaFuncAttributeMaxDynamicSharedMemorySize, SMEM_TOTAL);
    cudaFuncSetAttribute(gemm_hmma<4>, cudaFuncAttributeMaxDynamicSharedMemorySize, SMEM_TOTAL);

    __nv_bfloat16 *xh,*xl,*wqh,*wql,*wkh,*wkl,*wvh,*wvl,*woh,*wol;
    __nv_bfloat16 *qh,*ql,*kh,*kl,*vth,*vtl,*ah,*al,*ch,*cl;
    cudaGetSymbolAddress((void**)&xh,  g_xh);  cudaGetSymbolAddress((void**)&xl,  g_xl);
    cudaGetSymbolAddress((void**)&wqh, g_wqh); cudaGetSymbolAddress((void**)&wql, g_wql);
    cudaGetSymbolAddress((void**)&wkh, g_wkh); cudaGetSymbolAddress((void**)&wkl, g_wkl);
    cudaGetSymbolAddress((void**)&wvh, g_wvh); cudaGetSymbolAddress((void**)&wvl, g_wvl);
    cudaGetSymbolAddress((void**)&woh, g_woh); cudaGetSymbolAddress((void**)&wol, g_wol);
    cudaGetSymbolAddress((void**)&qh,  g_qh);  cudaGetSymbolAddress((void**)&ql,  g_ql);
    cudaGetSymbolAddress((void**)&kh,  g_kh);  cudaGetSymbolAddress((void**)&kl,  g_kl);
    cudaGetSymbolAddress((void**)&vth, g_vth); cudaGetSymbolAddress((void**)&vtl, g_vtl);
    cudaGetSymbolAddress((void**)&ah,  g_ah);  cudaGetSymbolAddress((void**)&al,  g_al);
    cudaGetSymbolAddress((void**)&ch,  g_ch);  cudaGetSymbolAddress((void**)&cl,  g_cl);

    // 1. splits
    split_kernel<<<OUT_ELEMS/256, 256>>>(x, xh, xl, OUT_ELEMS);
    dim3 tg(32, 32);
    splitT_kernel<<<dim3(32,32), tg>>>(Wq, wqh, wql);
    splitT_kernel<<<dim3(32,32), tg>>>(Wk, wkh, wkl);
    splitT_kernel<<<dim3(32,32), tg>>>(Wv, wvh, wvl);
    splitT_kernel<<<dim3(32,32), tg>>>(Wo, woh, wol);

    // 2. projections: A = x splits [8192,1024], B = WT splits [1024,1024]
    GP p{};
    p.Ah = xh; p.Al = xl; p.lda = 1024; p.ldb = 1024; p.K = 1024;
    p.strideAz = 0; p.strideBz = 0; p.scale = 1.f;
    dim3 gProj(8, 64, 1);
    p.Bh = wqh; p.Bl = wql; p.bias = bq; p.outH = qh;  p.outL = ql;
    gemm_hmma<0><<<gProj, 256, SMEM_TOTAL>>>(p);
    p.Bh = wkh; p.Bl = wkl; p.bias = bk; p.outH = kh;  p.outL = kl;
    gemm_hmma<0><<<gProj, 256, SMEM_TOTAL>>>(p);
    p.Bh = wvh; p.Bl = wvl; p.bias = bv; p.outH = vth; p.outL = vtl;
    gemm_hmma<1><<<gProj, 256, SMEM_TOTAL>>>(p);

    // 3. scores: per head, A=q [1024,128], B=k [1024,128], K=128
    GP ps{};
    ps.Ah = qh; ps.Al = ql; ps.Bh = kh; ps.Bl = kl;
    ps.strideAz = NDIM*DDIM; ps.strideBz = NDIM*DDIM;
    ps.lda = 128; ps.ldb = 128; ps.K = 128;
    ps.scale = 0.088388347648318440550f;
    ps.outF = attn;
    gemm_hmma<2><<<dim3(8, 8, HEADS), 256, SMEM_TOTAL>>>(ps);

    // 4. entmax (in place) + attn splits
    entmax_kernel<<<8192, 256>>>(attn, ah, al);

    // 5. ctx: per head, A=attn splits [1024,1024], B=vT [128,1024], K=1024
    GP pc{};
    pc.Ah = ah; pc.Al = al; pc.Bh = vth; pc.Bl = vtl;
    pc.strideAz = (long long)NDIM*NDIM; pc.strideBz = DDIM*NDIM;
    pc.lda = 1024; pc.ldb = 1024; pc.K = 1024;
    pc.scale = 1.f; pc.outH = ch; pc.outL = cl;
    gemm_hmma<3><<<dim3(1, 8, HEADS), 256, SMEM_TOTAL>>>(pc);

    // 6. out proj: A = ctx splits [8192,1024], B = WoT splits
    GP po{};
    po.Ah = ch; po.Al = cl; po.Bh = woh; po.Bl = wol;
    po.strideAz = 0; po.strideBz = 0;
    po.lda = 1024; po.ldb = 1024; po.K = 1024;
    po.scale = 1.f; po.bias = bo; po.outF = out;
    gemm_hmma<4><<<gProj, 256, SMEM_TOTAL>>>(po);
}

// round 4
// speedup vs baseline: 2.0521x; 1.0154x over previous
#include <cuda_runtime.h>
#include <cuda_bf16.h>
#include <cstdint>

// ===========================================================================
// EntmaxAttention B=8, N=1024, C=1024, H=8, D=128, alpha=1.5
// out  = [8,1024,1024]   -> d_out[0..8388608)
// attn = [8,8,1024,1024] -> d_out[8388608..75497472)
//
// Base sm_103 target: GEMMs via mma.sync m16n8k16 bf16 (HMMA), fp32 accum,
// 2-way bf16 split operands, 3-product compensation.
// ldmatrix fragment loads + 3-stage cp.async pipeline, 128x128 tiles, BK=32.
// ===========================================================================

#define BDIM 8
#define HDIM 8
#define NDIM 1024
#define CDIM 1024
#define DDIM 128
#define OUT_ELEMS (BDIM*NDIM*CDIM)
#define HEADS (BDIM*HDIM)

// smem geometry (bytes)
#define SAB 40                    // padded row stride in bf16 elements (80B)
#define ROWB 80
#define TILE_BYTES 10240          // 128 rows * 80B
#define STAGE_BYTES 40960         // Ah | Al | Bh | Bl
#define NSTAGE 3
#define SMEM_TOTAL (NSTAGE*STAGE_BYTES)

__device__ __forceinline__ uint32_t smem_u32(const void* p) {
    uint32_t a;
    asm("{ .reg .u64 t; cvta.to.shared.u64 t, %1; cvt.u32.u64 %0, t; }"
        : "=r"(a) : "l"(p));
    return a;
}
__device__ __forceinline__ void cpa16(uint32_t dst, const void* src) {
    asm volatile("cp.async.cg.shared.global [%0], [%1], 16;" :: "r"(dst), "l"(src));
}
__device__ __forceinline__ void cpa_commit() {
    asm volatile("cp.async.commit_group;" ::: "memory");
}
template<int N>
__device__ __forceinline__ void cpa_wait() {
    asm volatile("cp.async.wait_group %0;" :: "n"(N) : "memory");
}
__device__ __forceinline__ void mma16816(float* d, const uint32_t* a, const uint32_t* b) {
    asm volatile("mma.sync.aligned.m16n8k16.row.col.f32.bf16.bf16.f32 "
        "{%0,%1,%2,%3}, {%4,%5,%6,%7}, {%8,%9}, {%0,%1,%2,%3};"
        : "+f"(d[0]), "+f"(d[1]), "+f"(d[2]), "+f"(d[3])
        : "r"(a[0]), "r"(a[1]), "r"(a[2]), "r"(a[3]), "r"(b[0]), "r"(b[1]));
}
__device__ __forceinline__ void ldm_x4(uint32_t* r, uint32_t addr) {
    asm volatile("ldmatrix.sync.aligned.m8n8.x4.shared.b16 {%0,%1,%2,%3}, [%4];"
        : "=r"(r[0]), "=r"(r[1]), "=r"(r[2]), "=r"(r[3]) : "r"(addr));
}

// ------------------------- scratch (device globals) ------------------------
__device__ __nv_bfloat16 g_xh[OUT_ELEMS],  g_xl[OUT_ELEMS];
__device__ __nv_bfloat16 g_wqh[CDIM*CDIM], g_wql[CDIM*CDIM];
__device__ __nv_bfloat16 g_wkh[CDIM*CDIM], g_wkl[CDIM*CDIM];
__device__ __nv_bfloat16 g_wvh[CDIM*CDIM], g_wvl[CDIM*CDIM];
__device__ __nv_bfloat16 g_woh[CDIM*CDIM], g_wol[CDIM*CDIM];
__device__ __nv_bfloat16 g_qh[OUT_ELEMS],  g_ql[OUT_ELEMS];   // [BH,N,D]
__device__ __nv_bfloat16 g_kh[OUT_ELEMS],  g_kl[OUT_ELEMS];   // [BH,N,D]
__device__ __nv_bfloat16 g_vth[OUT_ELEMS], g_vtl[OUT_ELEMS];  // [BH,D,N]
__device__ __nv_bfloat16 g_ah[(size_t)HEADS*NDIM*NDIM], g_al[(size_t)HEADS*NDIM*NDIM];
__device__ __nv_bfloat16 g_ch[OUT_ELEMS],  g_cl[OUT_ELEMS];   // ctx [B,N,C]

// ------------------------- split kernels ------------------------------------
__global__ void __launch_bounds__(256) split_kernel(
    const float* __restrict__ src, __nv_bfloat16* __restrict__ hi,
    __nv_bfloat16* __restrict__ lo, int n)
{
    int i = blockIdx.x * 256 + threadIdx.x;
    if (i < n) {
        float v = src[i];
        __nv_bfloat16 h = __float2bfloat16(v);
        hi[i] = h;
        lo[i] = __float2bfloat16(v - __bfloat162float(h));
    }
}

// W [k,n] row-major -> WT hi/lo [n,k]
__global__ void __launch_bounds__(1024) splitT_kernel(
    const float* __restrict__ W, __nv_bfloat16* __restrict__ hiT,
    __nv_bfloat16* __restrict__ loT)
{
    __shared__ float t[32][33];
    int bx = blockIdx.x * 32, by = blockIdx.y * 32;
    int x = threadIdx.x, y = threadIdx.y;
    t[y][x] = W[(size_t)(by + y) * CDIM + bx + x];
    __syncthreads();
    float v = t[x][y];   // = W[by+x][bx+y]
    __nv_bfloat16 h = __float2bfloat16(v);
    size_t o = (size_t)(bx + y) * CDIM + by + x;
    hiT[o] = h;
    loT[o] = __float2bfloat16(v - __bfloat162float(h));
}

// ------------------------- generic HMMA GEMM --------------------------------
// D[m,n] = sum_k A[m,k]*B[n,k]  (both operands K-major), 128x128 tile, BK=32.
// MODE 0: QK proj  -> hi/lo at [B,H,N,D]          (+bias)
// MODE 1: V proj   -> hi/lo at vT [B,H,D,N]       (+bias)
// MODE 2: scores   -> fp32*scale at outF[z<<20]
// MODE 3: ctx      -> hi/lo at ctx [B,N,C]
// MODE 4: out proj -> fp32+bias at outF
struct GP {
    const __nv_bfloat16 *Ah, *Al, *Bh, *Bl;
    long long strideAz, strideBz;
    int lda, ldb, K;
    const float* bias;
    float scale;
    float* outF;
    __nv_bfloat16 *outH, *outL;
};

template<int MODE>
__global__ void __launch_bounds__(256) gemm_hmma(GP p)
{
    extern __shared__ char smem[];
    const uint32_t sbase = smem_u32(smem);
    const int tid = threadIdx.x;
    const int wid = tid >> 5;
    const int lane = tid & 31;
    const int g = lane >> 2;       // groupID 0..7
    const int tq = lane & 3;       // 0..3
    const int warp_m = (wid >> 2) * 64;   // 0 / 64
    const int warp_n = (wid & 3) * 32;    // 0..96
    const int z = blockIdx.z;
    const int row0 = blockIdx.y * 128;
    const int col0 = blockIdx.x * 128;

    const __nv_bfloat16* Ah = p.Ah + (size_t)z * p.strideAz;
    const __nv_bfloat16* Al = p.Al + (size_t)z * p.strideAz;
    const __nv_bfloat16* Bh = p.Bh + (size_t)z * p.strideBz;
    const __nv_bfloat16* Bl = p.Bl + (size_t)z * p.strideBz;

    float acc[4][4][4];
    #pragma unroll
    for (int i = 0; i < 4; i++)
        #pragma unroll
        for (int j = 0; j < 4; j++)
            #pragma unroll
            for (int e = 0; e < 4; e++) acc[i][j][e] = 0.f;

    const int nchunk = p.K >> 5;

    // ldmatrix per-lane base offsets (bytes, within a tile)
    // A frag (i, s16): rows warp_m+i*16+(lane&15), k = s16*16 + (lane>>4)*8
    const uint32_t a_off = (uint32_t)((warp_m + (lane & 15)) * ROWB + (lane >> 4) * 16);
    // B frag pair (jp, s16): rows warp_n+jp*16+(lane&7)+((lane>>4)<<3),
    //                        k = s16*16 + ((lane>>3)&1)*8
    const uint32_t b_off = (uint32_t)((warp_n + (lane & 7) + ((lane >> 4) << 3)) * ROWB
                                      + ((lane >> 3) & 1) * 16);

    auto prefetch = [&](int c) {
        int s = c % NSTAGE;
        int k0 = c << 5;
        uint32_t sb = sbase + s * STAGE_BYTES;
        #pragma unroll
        for (int it = 0; it < 2; it++) {
            int id = tid + it * 256;
            int r = id >> 2;
            int ch = id & 3;
            uint32_t doff = (uint32_t)(r * ROWB + ch * 16);
            size_t ga = (size_t)(row0 + r) * p.lda + k0 + ch * 8;
            size_t gb = (size_t)(col0 + r) * p.ldb + k0 + ch * 8;
            cpa16(sb + doff,                   Ah + ga);
            cpa16(sb + TILE_BYTES + doff,      Al + ga);
            cpa16(sb + 2*TILE_BYTES + doff,    Bh + gb);
            cpa16(sb + 3*TILE_BYTES + doff,    Bl + gb);
        }
        cpa_commit();
    };

    prefetch(0);
    if (nchunk > 1) prefetch(1);

    for (int c = 0; c < nchunk; c++) {
        if (c + 1 < nchunk) cpa_wait<1>(); else cpa_wait<0>();
        __syncthreads();
        if (c + 2 < nchunk) prefetch(c + 2);

        uint32_t stg = sbase + (uint32_t)((c % NSTAGE) * STAGE_BYTES);

        #pragma unroll
        for (int s16 = 0; s16 < 2; s16++) {
            const uint32_t koffb = (uint32_t)(s16 * 32);
            uint32_t bh[4][2], bl[4][2];
            #pragma unroll
            for (int jp = 0; jp < 2; jp++) {
                uint32_t ba = stg + b_off + koffb + (uint32_t)(jp * 16 * ROWB);
                uint32_t r4[4];
                ldm_x4(r4, ba + 2*TILE_BYTES);
                bh[jp*2][0] = r4[0]; bh[jp*2][1] = r4[1];
                bh[jp*2+1][0] = r4[2]; bh[jp*2+1][1] = r4[3];
                ldm_x4(r4, ba + 3*TILE_BYTES);
                bl[jp*2][0] = r4[0]; bl[jp*2][1] = r4[1];
                bl[jp*2+1][0] = r4[2]; bl[jp*2+1][1] = r4[3];
            }
            uint32_t ah[4][4], al[4][4];
            #pragma unroll
            for (int i = 0; i < 4; i++) {
                uint32_t aa = stg + a_off + koffb + (uint32_t)(i * 16 * ROWB);
                ldm_x4(ah[i], aa);
                ldm_x4(al[i], aa + TILE_BYTES);
            }
            #pragma unroll
            for (int i = 0; i < 4; i++)
                #pragma unroll
                for (int j = 0; j < 4; j++) {
                    mma16816(acc[i][j], ah[i], bh[j]);
                    mma16816(acc[i][j], ah[i], bl[j]);
                    mma16816(acc[i][j], al[i], bh[j]);
                }
        }
        __syncthreads();
    }

    // --- epilogue ---
    #pragma unroll
    for (int i = 0; i < 4; i++) {
        #pragma unroll
        for (int j = 0; j < 4; j++) {
            #pragma unroll
            for (int e = 0; e < 4; e++) {
                int m  = row0 + warp_m + i*16 + g + ((e >> 1) ? 8 : 0);
                int cc = col0 + warp_n + j*8 + tq*2 + (e & 1);
                float val = acc[i][j][e];
                if (MODE == 0) {
                    float v = val + p.bias[cc];
                    int b = m >> 10, nn = m & 1023;
                    int h = cc >> 7, d = cc & 127;
                    size_t o = ((size_t)(((b*8 + h) << 10) + nn)) * 128 + d;
                    __nv_bfloat16 hh = __float2bfloat16(v);
                    p.outH[o] = hh;
                    p.outL[o] = __float2bfloat16(v - __bfloat162float(hh));
                } else if (MODE == 1) {
                    float v = val + p.bias[cc];
                    int b = m >> 10, nn = m & 1023;
                    int h = cc >> 7, d = cc & 127;
                    size_t o = ((size_t)(((b*8 + h) << 7) + d)) * 1024 + nn;
                    __nv_bfloat16 hh = __float2bfloat16(v);
                    p.outH[o] = hh;
                    p.outL[o] = __float2bfloat16(v - __bfloat162float(hh));
                } else if (MODE == 2) {
                    p.outF[((size_t)z << 20) + (size_t)m * 1024 + cc] = val * p.scale;
                } else if (MODE == 3) {
                    int b = z >> 3, h = z & 7;
                    size_t o = ((size_t)((b << 10) + m)) * 1024 + h * 128 + cc;
                    __nv_bfloat16 hh = __float2bfloat16(val);
                    p.outH[o] = hh;
                    p.outL[o] = __float2bfloat16(val - __bfloat162float(hh));
                } else {
                    p.outF[(size_t)m * 1024 + cc] = val + p.bias[cc];
                }
            }
        }
    }
}

// ------------------------- entmax (in place, + bf16 splits) ----------------
__global__ void __launch_bounds__(256) entmax_kernel(
    float* __restrict__ attn, __nv_bfloat16* __restrict__ ah,
    __nv_bfloat16* __restrict__ al)
{
    int gwarp = (blockIdx.x * blockDim.x + threadIdx.x) >> 5;
    int lane  = threadIdx.x & 31;
    size_t rbase = (size_t)gwarp * 1024;
    float* row = attn + rbase;

    float xm[32];
    #pragma unroll
    for (int i = 0; i < 32; i++) xm[i] = 0.5f * row[i*32 + lane];

    float mx = xm[0];
    #pragma unroll
    for (int i = 1; i < 32; i++) mx = fmaxf(mx, xm[i]);
    #pragma unroll
    for (int o = 16; o > 0; o >>= 1)
        mx = fmaxf(mx, __shfl_xor_sync(0xffffffffu, mx, o));

    float tau_lo = mx - 1.0f;
    float dm = 1.0f - 0.03125f;

    float s = 0.f;
    #pragma unroll
    for (int i = 0; i < 32; i++) {
        float t = fmaxf(xm[i] - tau_lo, 0.f);
        s = fmaf(t, t, s);
    }
    #pragma unroll
    for (int o = 16; o > 0; o >>= 1)
        s += __shfl_xor_sync(0xffffffffu, s, o);
    float f_lo = s - 1.0f;

    float tau_m = tau_lo;
    #pragma unroll 1
    for (int it = 0; it < 34; it++) {
        dm *= 0.5f;
        tau_m = tau_lo + dm;
        float fs = 0.f;
        #pragma unroll
        for (int i = 0; i < 32; i++) {
            float t = fmaxf(xm[i] - tau_m, 0.f);
            fs = fmaf(t, t, fs);
        }
        #pragma unroll
        for (int o = 16; o > 0; o >>= 1)
            fs += __shfl_xor_sync(0xffffffffu, fs, o);
        if ((fs - 1.0f) * f_lo >= 0.f) tau_lo = tau_m;
    }

    float pv[32];
    float psum = 0.f;
    #pragma unroll
    for (int i = 0; i < 32; i++) {
        float t = fmaxf(xm[i] - tau_m, 0.f);
        pv[i] = t * t;
        psum += pv[i];
    }
    #pragma unroll
    for (int o = 16; o > 0; o >>= 1)
        psum += __shfl_xor_sync(0xffffffffu, psum, o);
    float inv = 1.0f / psum;
    #pragma unroll
    for (int i = 0; i < 32; i++) {
        float v = pv[i] * inv;
        int idx = i*32 + lane;
        row[idx] = v;
        __nv_bfloat16 hh = __float2bfloat16(v);
        ah[rbase + idx] = hh;
        al[rbase + idx] = __float2bfloat16(v - __bfloat162float(hh));
    }
}

// ---------------------------------------------------------------------------
extern "C" void kernel_launch(void* const* d_in, const int* in_sizes, int n_in,
                              void* d_out, int out_size)
{
    const float* x  = (const float*)d_in[0];
    const float* Wq = (const float*)d_in[1];
    const float* bq = (const float*)d_in[2];
    const float* Wk = (const float*)d_in[3];
    const float* bk = (const float*)d_in[4];
    const float* Wv = (const float*)d_in[5];
    const float* bv = (const float*)d_in[6];
    const float* Wo = (const float*)d_in[7];
    const float* bo = (const float*)d_in[8];

    float* out  = (float*)d_out;
    float* attn = out + OUT_ELEMS;

    cudaFuncSetAttribute(gemm_hmma<0>, cudaFuncAttributeMaxDynamicSharedMemorySize, SMEM_TOTAL);
    cudaFuncSetAttribute(gemm_hmma<1>, cudaFuncAttributeMaxDynamicSharedMemorySize, SMEM_TOTAL);
    cudaFuncSetAttribute(gemm_hmma<2>, cudaFuncAttributeMaxDynamicSharedMemorySize, SMEM_TOTAL);
    cudaFuncSetAttribute(gemm_hmma<3>, cudaFuncAttributeMaxDynamicSharedMemorySize, SMEM_TOTAL);
    cudaFuncSetAttribute(gemm_hmma<4>, cudaFuncAttributeMaxDynamicSharedMemorySize, SMEM_TOTAL);

    __nv_bfloat16 *xh,*xl,*wqh,*wql,*wkh,*wkl,*wvh,*wvl,*woh,*wol;
    __nv_bfloat16 *qh,*ql,*kh,*kl,*vth,*vtl,*ah,*al,*ch,*cl;
    cudaGetSymbolAddress((void**)&xh,  g_xh);  cudaGetSymbolAddress((void**)&xl,  g_xl);
    cudaGetSymbolAddress((void**)&wqh, g_wqh); cudaGetSymbolAddress((void**)&wql, g_wql);
    cudaGetSymbolAddress((void**)&wkh, g_wkh); cudaGetSymbolAddress((void**)&wkl, g_wkl);
    cudaGetSymbolAddress((void**)&wvh, g_wvh); cudaGetSymbolAddress((void**)&wvl, g_wvl);
    cudaGetSymbolAddress((void**)&woh, g_woh); cudaGetSymbolAddress((void**)&wol, g_wol);
    cudaGetSymbolAddress((void**)&qh,  g_qh);  cudaGetSymbolAddress((void**)&ql,  g_ql);
    cudaGetSymbolAddress((void**)&kh,  g_kh);  cudaGetSymbolAddress((void**)&kl,  g_kl);
    cudaGetSymbolAddress((void**)&vth, g_vth); cudaGetSymbolAddress((void**)&vtl, g_vtl);
    cudaGetSymbolAddress((void**)&ah,  g_ah);  cudaGetSymbolAddress((void**)&al,  g_al);
    cudaGetSymbolAddress((void**)&ch,  g_ch);  cudaGetSymbolAddress((void**)&cl,  g_cl);

    // 1. splits
    split_kernel<<<OUT_ELEMS/256, 256>>>(x, xh, xl, OUT_ELEMS);
    dim3 tg(32, 32);
    splitT_kernel<<<dim3(32,32), tg>>>(Wq, wqh, wql);
    splitT_kernel<<<dim3(32,32), tg>>>(Wk, wkh, wkl);
    splitT_kernel<<<dim3(32,32), tg>>>(Wv, wvh, wvl);
    splitT_kernel<<<dim3(32,32), tg>>>(Wo, woh, wol);

    // 2. projections: A = x splits [8192,1024], B = WT splits [1024,1024]
    GP p{};
    p.Ah = xh; p.Al = xl; p.lda = 1024; p.ldb = 1024; p.K = 1024;
    p.strideAz = 0; p.strideBz = 0; p.scale = 1.f;
    dim3 gProj(8, 64, 1);
    p.Bh = wqh; p.Bl = wql; p.bias = bq; p.outH = qh;  p.outL = ql;
    gemm_hmma<0><<<gProj, 256, SMEM_TOTAL>>>(p);
    p.Bh = wkh; p.Bl = wkl; p.bias = bk; p.outH = kh;  p.outL = kl;
    gemm_hmma<0><<<gProj, 256, SMEM_TOTAL>>>(p);
    p.Bh = wvh; p.Bl = wvl; p.bias = bv; p.outH = vth; p.outL = vtl;
    gemm_hmma<1><<<gProj, 256, SMEM_TOTAL>>>(p);

    // 3. scores: per head, A=q [1024,128], B=k [1024,128], K=128
    GP ps{};
    ps.Ah = qh; ps.Al = ql; ps.Bh = kh; ps.Bl = kl;
    ps.strideAz = NDIM*DDIM; ps.strideBz = NDIM*DDIM;
    ps.lda = 128; ps.ldb = 128; ps.K = 128;
    ps.scale = 0.088388347648318440550f;
    ps.outF = attn;
    gemm_hmma<2><<<dim3(8, 8, HEADS), 256, SMEM_TOTAL>>>(ps);

    // 4. entmax (in place) + attn splits
    entmax_kernel<<<8192, 256>>>(attn, ah, al);

    // 5. ctx: per head, A=attn splits [1024,1024], B=vT [128,1024], K=1024
    GP pc{};
    pc.Ah = ah; pc.Al = al; pc.Bh = vth; pc.Bl = vtl;
    pc.strideAz = (long long)NDIM*NDIM; pc.strideBz = DDIM*NDIM;
    pc.lda = 1024; pc.ldb = 1024; pc.K = 1024;
    pc.scale = 1.f; pc.outH = ch; pc.outL = cl;
    gemm_hmma<3><<<dim3(1, 8, HEADS), 256, SMEM_TOTAL>>>(pc);

    // 6. out proj: A = ctx splits [8192,1024], B = WoT splits
    GP po{};
    po.Ah = ch; po.Al = cl; po.Bh = woh; po.Bl = wol;
    po.strideAz = 0; po.strideBz = 0;
    po.lda = 1024; po.ldb = 1024; po.K = 1024;
    po.scale = 1.f; po.bias = bo; po.outF = out;
    gemm_hmma<4><<<gProj, 256, SMEM_TOTAL>>>(po);
}

// round 5
// speedup vs baseline: 2.3969x; 1.1680x over previous
#include <cuda_runtime.h>
#include <cuda_fp16.h>
#include <cstdint>

// ===========================================================================
// EntmaxAttention B=8, N=1024, C=1024, H=8, D=128, alpha=1.5
// out  = [8,1024,1024]   -> d_out[0..8388608)
// attn = [8,8,1024,1024] -> d_out[8388608..75497472)
//
// Base sm_103 target: GEMMs via mma.sync m16n8k16 fp16 (HMMA), fp32 accum.
// Scores chain (Q,K proj + scores): 2-way fp16 split both operands, 3 products.
// Value chain (V proj, ctx, out proj): A split + B single fp16, 2 products.
// ldmatrix fragment loads + 3-stage cp.async pipeline, 128x128 tiles, BK=32.
// ===========================================================================

#define BDIM 8
#define HDIM 8
#define NDIM 1024
#define CDIM 1024
#define DDIM 128
#define OUT_ELEMS (BDIM*NDIM*CDIM)
#define HEADS (BDIM*HDIM)

#define ROWB 80                   // padded row stride (bytes) = 40 halves
#define TILE_BYTES 10240          // 128 rows * 80B
#define NSTAGE 3

__device__ __forceinline__ uint32_t smem_u32(const void* p) {
    uint32_t a;
    asm("{ .reg .u64 t; cvta.to.shared.u64 t, %1; cvt.u32.u64 %0, t; }"
        : "=r"(a) : "l"(p));
    return a;
}
__device__ __forceinline__ void cpa16(uint32_t dst, const void* src) {
    asm volatile("cp.async.cg.shared.global [%0], [%1], 16;" :: "r"(dst), "l"(src));
}
__device__ __forceinline__ void cpa_commit() {
    asm volatile("cp.async.commit_group;" ::: "memory");
}
template<int N>
__device__ __forceinline__ void cpa_wait() {
    asm volatile("cp.async.wait_group %0;" :: "n"(N) : "memory");
}
__device__ __forceinline__ void mma16816(float* d, const uint32_t* a, const uint32_t* b) {
    asm volatile("mma.sync.aligned.m16n8k16.row.col.f32.f16.f16.f32 "
        "{%0,%1,%2,%3}, {%4,%5,%6,%7}, {%8,%9}, {%0,%1,%2,%3};"
        : "+f"(d[0]), "+f"(d[1]), "+f"(d[2]), "+f"(d[3])
        : "r"(a[0]), "r"(a[1]), "r"(a[2]), "r"(a[3]), "r"(b[0]), "r"(b[1]));
}
__device__ __forceinline__ void ldm_x4(uint32_t* r, uint32_t addr) {
    asm volatile("ldmatrix.sync.aligned.m8n8.x4.shared.b16 {%0,%1,%2,%3}, [%4];"
        : "=r"(r[0]), "=r"(r[1]), "=r"(r[2]), "=r"(r[3]) : "r"(addr));
}

// ------------------------- scratch (device globals) ------------------------
__device__ __half g_xh[OUT_ELEMS],  g_xl[OUT_ELEMS];
__device__ __half g_wqh[CDIM*CDIM], g_wql[CDIM*CDIM];
__device__ __half g_wkh[CDIM*CDIM], g_wkl[CDIM*CDIM];
__device__ __half g_wvt[CDIM*CDIM];                       // WvT single fp16
__device__ __half g_wot[CDIM*CDIM];                       // WoT single fp16
__device__ __half g_qh[OUT_ELEMS],  g_ql[OUT_ELEMS];      // [BH,N,D]
__device__ __half g_kh[OUT_ELEMS],  g_kl[OUT_ELEMS];      // [BH,N,D]
__device__ __half g_vt[OUT_ELEMS];                        // [BH,D,N] single
__device__ __half g_ah[(size_t)HEADS*NDIM*NDIM], g_al[(size_t)HEADS*NDIM*NDIM];
__device__ __half g_ch[OUT_ELEMS],  g_cl[OUT_ELEMS];      // ctx [B,N,C] split

// ------------------------- prep kernels -------------------------------------
__global__ void __launch_bounds__(256) split_kernel(
    const float* __restrict__ src, __half* __restrict__ hi,
    __half* __restrict__ lo, int n)
{
    int i = blockIdx.x * 256 + threadIdx.x;
    if (i < n) {
        float v = src[i];
        __half h = __float2half(v);
        hi[i] = h;
        lo[i] = __float2half(v - __half2float(h));
    }
}

// z=0: Wq -> wqh/wql (T), z=1: Wk -> wkh/wkl (T)
__global__ void __launch_bounds__(1024) splitT2_kernel(
    const float* __restrict__ W0, const float* __restrict__ W1,
    __half* __restrict__ h0, __half* __restrict__ l0,
    __half* __restrict__ h1, __half* __restrict__ l1)
{
    const float* W = blockIdx.z ? W1 : W0;
    __half* hiT = blockIdx.z ? h1 : h0;
    __half* loT = blockIdx.z ? l1 : l0;
    __shared__ float t[32][33];
    int bx = blockIdx.x * 32, by = blockIdx.y * 32;
    int x = threadIdx.x, y = threadIdx.y;
    t[y][x] = W[(size_t)(by + y) * CDIM + bx + x];
    __syncthreads();
    float v = t[x][y];   // = W[by+x][bx+y]
    __half h = __float2half(v);
    size_t o = (size_t)(bx + y) * CDIM + by + x;
    hiT[o] = h;
    loT[o] = __float2half(v - __half2float(h));
}

// z=0: Wv -> wvt (T single), z=1: Wo -> wot (T single)
__global__ void __launch_bounds__(1024) cvtT2_kernel(
    const float* __restrict__ W0, const float* __restrict__ W1,
    __half* __restrict__ t0, __half* __restrict__ t1)
{
    const float* W = blockIdx.z ? W1 : W0;
    __half* hT = blockIdx.z ? t1 : t0;
    __shared__ float t[32][33];
    int bx = blockIdx.x * 32, by = blockIdx.y * 32;
    int x = threadIdx.x, y = threadIdx.y;
    t[y][x] = W[(size_t)(by + y) * CDIM + bx + x];
    __syncthreads();
    hT[(size_t)(bx + y) * CDIM + by + x] = __float2half(t[x][y]);
}

// ------------------------- generic HMMA GEMM --------------------------------
// D[m,n] = sum_k A[m,k]*B[n,k]  (both K-major), 128x128 tile, BK=32.
// NPROD 3: A=Ah+Al, B=Bh+Bl; products AhBh + AhBl + AlBh  (stage: Ah|Al|Bh|Bl)
// NPROD 2: A=Ah+Al, B=Bh single; products AhB + AlB       (stage: Ah|Al|B)
// MODE 0: QK proj  -> hi/lo fp16 at [B,H,N,D]     (+bias)
// MODE 1: V proj   -> single fp16 at vT [B,H,D,N] (+bias)
// MODE 2: scores   -> fp32*scale at outF[z<<20]
// MODE 3: ctx      -> hi/lo fp16 at ctx [B,N,C]
// MODE 4: out proj -> fp32+bias at outF
struct GP {
    const __half *Ah, *Al, *Bh, *Bl;
    long long strideAz, strideBz;
    int lda, ldb, K;
    const float* bias;
    float scale;
    float* outF;
    __half *outH, *outL;
};

template<int MODE, int NPROD>
__global__ void __launch_bounds__(256) gemm_hmma(GP p)
{
    constexpr int NT = (NPROD == 3) ? 4 : 3;
    constexpr uint32_t STAGE = NT * TILE_BYTES;
    extern __shared__ char smem[];
    const uint32_t sbase = smem_u32(smem);
    const int tid = threadIdx.x;
    const int wid = tid >> 5;
    const int lane = tid & 31;
    const int g = lane >> 2;
    const int tq = lane & 3;
    const int warp_m = (wid >> 2) * 64;
    const int warp_n = (wid & 3) * 32;
    const int z = blockIdx.z;
    const int row0 = blockIdx.y * 128;
    const int col0 = blockIdx.x * 128;

    const __half* Ah = p.Ah + (size_t)z * p.strideAz;
    const __half* Al = p.Al + (size_t)z * p.strideAz;
    const __half* Bh = p.Bh + (size_t)z * p.strideBz;
    const __half* Bl = (NPROD == 3) ? (p.Bl + (size_t)z * p.strideBz) : nullptr;

    float acc[4][4][4];
    #pragma unroll
    for (int i = 0; i < 4; i++)
        #pragma unroll
        for (int j = 0; j < 4; j++)
            #pragma unroll
            for (int e = 0; e < 4; e++) acc[i][j][e] = 0.f;

    const int nchunk = p.K >> 5;

    const uint32_t a_off = (uint32_t)((warp_m + (lane & 15)) * ROWB + (lane >> 4) * 16);
    const uint32_t b_off = (uint32_t)((warp_n + (lane & 7) + ((lane >> 4) << 3)) * ROWB
                                      + ((lane >> 3) & 1) * 16);

    auto prefetch = [&](int c) {
        int s = c % NSTAGE;
        int k0 = c << 5;
        uint32_t sb = sbase + s * STAGE;
        #pragma unroll
        for (int it = 0; it < 2; it++) {
            int id = tid + it * 256;
            int r = id >> 2;
            int ch = id & 3;
            uint32_t doff = (uint32_t)(r * ROWB + ch * 16);
            size_t ga = (size_t)(row0 + r) * p.lda + k0 + ch * 8;
            size_t gb = (size_t)(col0 + r) * p.ldb + k0 + ch * 8;
            cpa16(sb + doff,                Ah + ga);
            cpa16(sb + TILE_BYTES + doff,   Al + ga);
            cpa16(sb + 2*TILE_BYTES + doff, Bh + gb);
            if (NPROD == 3)
                cpa16(sb + 3*TILE_BYTES + doff, Bl + gb);
        }
        cpa_commit();
    };

    prefetch(0);
    if (nchunk > 1) prefetch(1);

    for (int c = 0; c < nchunk; c++) {
        if (c + 1 < nchunk) cpa_wait<1>(); else cpa_wait<0>();
        __syncthreads();
        if (c + 2 < nchunk) prefetch(c + 2);

        uint32_t stg = sbase + (uint32_t)((c % NSTAGE) * STAGE);

        #pragma unroll
        for (int s16 = 0; s16 < 2; s16++) {
            const uint32_t koffb = (uint32_t)(s16 * 32);
            uint32_t bh[4][2], bl[4][2];
            #pragma unroll
            for (int jp = 0; jp < 2; jp++) {
                uint32_t ba = stg + b_off + koffb + (uint32_t)(jp * 16 * ROWB);
                uint32_t r4[4];
                ldm_x4(r4, ba + 2*TILE_BYTES);
                bh[jp*2][0] = r4[0]; bh[jp*2][1] = r4[1];
                bh[jp*2+1][0] = r4[2]; bh[jp*2+1][1] = r4[3];
                if (NPROD == 3) {
                    ldm_x4(r4, ba + 3*TILE_BYTES);
                    bl[jp*2][0] = r4[0]; bl[jp*2][1] = r4[1];
                    bl[jp*2+1][0] = r4[2]; bl[jp*2+1][1] = r4[3];
                }
            }
            uint32_t ah[4][4], al[4][4];
            #pragma unroll
            for (int i = 0; i < 4; i++) {
                uint32_t aa = stg + a_off + koffb + (uint32_t)(i * 16 * ROWB);
                ldm_x4(ah[i], aa);
                ldm_x4(al[i], aa + TILE_BYTES);
            }
            #pragma unroll
            for (int i = 0; i < 4; i++)
                #pragma unroll
                for (int j = 0; j < 4; j++) {
                    mma16816(acc[i][j], ah[i], bh[j]);
                    if (NPROD == 3) mma16816(acc[i][j], ah[i], bl[j]);
                    mma16816(acc[i][j], al[i], bh[j]);
                }
        }
        __syncthreads();
    }

    // --- epilogue ---
    #pragma unroll
    for (int i = 0; i < 4; i++) {
        #pragma unroll
        for (int j = 0; j < 4; j++) {
            #pragma unroll
            for (int e = 0; e < 4; e++) {
                int m  = row0 + warp_m + i*16 + g + ((e >> 1) ? 8 : 0);
                int cc = col0 + warp_n + j*8 + tq*2 + (e & 1);
                float val = acc[i][j][e];
                if (MODE == 0) {
                    float v = val + p.bias[cc];
                    int b = m >> 10, nn = m & 1023;
                    int h = cc >> 7, d = cc & 127;
                    size_t o = ((size_t)(((b*8 + h) << 10) + nn)) * 128 + d;
                    __half hh = __float2half(v);
                    p.outH[o] = hh;
                    p.outL[o] = __float2half(v - __half2float(hh));
                } else if (MODE == 1) {
                    float v = val + p.bias[cc];
                    int b = m >> 10, nn = m & 1023;
                    int h = cc >> 7, d = cc & 127;
                    size_t o = ((size_t)(((b*8 + h) << 7) + d)) * 1024 + nn;
                    p.outH[o] = __float2half(v);
                } else if (MODE == 2) {
                    p.outF[((size_t)z << 20) + (size_t)m * 1024 + cc] = val * p.scale;
                } else if (MODE == 3) {
                    int b = z >> 3, h = z & 7;
                    size_t o = ((size_t)((b << 10) + m)) * 1024 + h * 128 + cc;
                    __half hh = __float2half(val);
                    p.outH[o] = hh;
                    p.outL[o] = __float2half(val - __half2float(hh));
                } else {
                    p.outF[(size_t)m * 1024 + cc] = val + p.bias[cc];
                }
            }
        }
    }
}

// ------------------------- entmax (in place, + fp16 splits) ----------------
__global__ void __launch_bounds__(256) entmax_kernel(
    float* __restrict__ attn, __half* __restrict__ ah,
    __half* __restrict__ al)
{
    int gwarp = (blockIdx.x * blockDim.x + threadIdx.x) >> 5;
    int lane  = threadIdx.x & 31;
    size_t rbase = (size_t)gwarp * 1024;
    float* row = attn + rbase;

    float xm[32];
    #pragma unroll
    for (int i = 0; i < 32; i++) xm[i] = 0.5f * row[i*32 + lane];

    float mx = xm[0];
    #pragma unroll
    for (int i = 1; i < 32; i++) mx = fmaxf(mx, xm[i]);
    #pragma unroll
    for (int o = 16; o > 0; o >>= 1)
        mx = fmaxf(mx, __shfl_xor_sync(0xffffffffu, mx, o));

    float tau_lo = mx - 1.0f;
    float dm = 1.0f - 0.03125f;

    float s = 0.f;
    #pragma unroll
    for (int i = 0; i < 32; i++) {
        float t = fmaxf(xm[i] - tau_lo, 0.f);
        s = fmaf(t, t, s);
    }
    #pragma unroll
    for (int o = 16; o > 0; o >>= 1)
        s += __shfl_xor_sync(0xffffffffu, s, o);
    float f_lo = s - 1.0f;

    float tau_m = tau_lo;
    #pragma unroll 1
    for (int it = 0; it < 34; it++) {
        dm *= 0.5f;
        tau_m = tau_lo + dm;
        float fs = 0.f;
        #pragma unroll
        for (int i = 0; i < 32; i++) {
            float t = fmaxf(xm[i] - tau_m, 0.f);
            fs = fmaf(t, t, fs);
        }
        #pragma unroll
        for (int o = 16; o > 0; o >>= 1)
            fs += __shfl_xor_sync(0xffffffffu, fs, o);
        if ((fs - 1.0f) * f_lo >= 0.f) tau_lo = tau_m;
    }

    float pv[32];
    float psum = 0.f;
    #pragma unroll
    for (int i = 0; i < 32; i++) {
        float t = fmaxf(xm[i] - tau_m, 0.f);
        pv[i] = t * t;
        psum += pv[i];
    }
    #pragma unroll
    for (int o = 16; o > 0; o >>= 1)
        psum += __shfl_xor_sync(0xffffffffu, psum, o);
    float inv = 1.0f / psum;
    #pragma unroll
    for (int i = 0; i < 32; i++) {
        float v = pv[i] * inv;
        int idx = i*32 + lane;
        row[idx] = v;
        __half hh = __float2half(v);
        ah[rbase + idx] = hh;
        al[rbase + idx] = __float2half(v - __half2float(hh));
    }
}

// ---------------------------------------------------------------------------
extern "C" void kernel_launch(void* const* d_in, const int* in_sizes, int n_in,
                              void* d_out, int out_size)
{
    const float* x  = (const float*)d_in[0];
    const float* Wq = (const float*)d_in[1];
    const float* bq = (const float*)d_in[2];
    const float* Wk = (const float*)d_in[3];
    const float* bk = (const float*)d_in[4];
    const float* Wv = (const float*)d_in[5];
    const float* bv = (const float*)d_in[6];
    const float* Wo = (const float*)d_in[7];
    const float* bo = (const float*)d_in[8];

    float* out  = (float*)d_out;
    float* attn = out + OUT_ELEMS;

    const int SMEM3 = NSTAGE * 4 * TILE_BYTES;   // 122880
    const int SMEM2 = NSTAGE * 3 * TILE_BYTES;   //  92160
    cudaFuncSetAttribute((const void*)gemm_hmma<0,3>, cudaFuncAttributeMaxDynamicSharedMemorySize, SMEM3);
    cudaFuncSetAttribute((const void*)gemm_hmma<1,2>, cudaFuncAttributeMaxDynamicSharedMemorySize, SMEM2);
    cudaFuncSetAttribute((const void*)gemm_hmma<2,3>, cudaFuncAttributeMaxDynamicSharedMemorySize, SMEM3);
    cudaFuncSetAttribute((const void*)gemm_hmma<3,2>, cudaFuncAttributeMaxDynamicSharedMemorySize, SMEM2);
    cudaFuncSetAttribute((const void*)gemm_hmma<4,2>, cudaFuncAttributeMaxDynamicSharedMemorySize, SMEM2);

    __half *xh,*xl,*wqh,*wql,*wkh,*wkl,*wvt,*wot;
    __half *qh,*ql,*kh,*kl,*vt,*ah,*al,*ch,*cl;
    cudaGetSymbolAddress((void**)&xh,  g_xh);  cudaGetSymbolAddress((void**)&xl,  g_xl);
    cudaGetSymbolAddress((void**)&wqh, g_wqh); cudaGetSymbolAddress((void**)&wql, g_wql);
    cudaGetSymbolAddress((void**)&wkh, g_wkh); cudaGetSymbolAddress((void**)&wkl, g_wkl);
    cudaGetSymbolAddress((void**)&wvt, g_wvt); cudaGetSymbolAddress((void**)&wot, g_wot);
    cudaGetSymbolAddress((void**)&qh,  g_qh);  cudaGetSymbolAddress((void**)&ql,  g_ql);
    cudaGetSymbolAddress((void**)&kh,  g_kh);  cudaGetSymbolAddress((void**)&kl,  g_kl);
    cudaGetSymbolAddress((void**)&vt,  g_vt);
    cudaGetSymbolAddress((void**)&ah,  g_ah);  cudaGetSymbolAddress((void**)&al,  g_al);
    cudaGetSymbolAddress((void**)&ch,  g_ch);  cudaGetSymbolAddress((void**)&cl,  g_cl);

    // 1. prep (3 launches)
    split_kernel<<<OUT_ELEMS/256, 256>>>(x, xh, xl, OUT_ELEMS);
    dim3 tg(32, 32);
    splitT2_kernel<<<dim3(32,32,2), tg>>>(Wq, Wk, wqh, wql, wkh, wkl);
    cvtT2_kernel<<<dim3(32,32,2), tg>>>(Wv, Wo, wvt, wot);

    dim3 gProj(8, 64, 1);

    // 2. V proj (2-product): A = x split, B = WvT single -> vT single fp16
    GP pv{};
    pv.Ah = xh; pv.Al = xl; pv.Bh = wvt; pv.Bl = nullptr;
    pv.strideAz = 0; pv.strideBz = 0;
    pv.lda = 1024; pv.ldb = 1024; pv.K = 1024;
    pv.bias = bv; pv.scale = 1.f; pv.outH = vt;
    gemm_hmma<1,2><<<gProj, 256, SMEM2>>>(pv);

    // 3. Q,K proj (3-product)
    GP p{};
    p.Ah = xh; p.Al = xl; p.lda = 1024; p.ldb = 1024; p.K = 1024;
    p.strideAz = 0; p.strideBz = 0; p.scale = 1.f;
    p.Bh = wqh; p.Bl = wql; p.bias = bq; p.outH = qh; p.outL = ql;
    gemm_hmma<0,3><<<gProj, 256, SMEM3>>>(p);
    p.Bh = wkh; p.Bl = wkl; p.bias = bk; p.outH = kh; p.outL = kl;
    gemm_hmma<0,3><<<gProj, 256, SMEM3>>>(p);

    // 4. scores (3-product): per head, K=128
    GP ps{};
    ps.Ah = qh; ps.Al = ql; ps.Bh = kh; ps.Bl = kl;
    ps.strideAz = NDIM*DDIM; ps.strideBz = NDIM*DDIM;
    ps.lda = 128; ps.ldb = 128; ps.K = 128;
    ps.scale = 0.088388347648318440550f;
    ps.outF = attn;
    gemm_hmma<2,3><<<dim3(8, 8, HEADS), 256, SMEM3>>>(ps);

    // 5. entmax (in place) + fp16 splits
    entmax_kernel<<<8192, 256>>>(attn, ah, al);

    // 6. ctx (2-product): A = attn split, B = vT single, K=1024
    GP pc{};
    pc.Ah = ah; pc.Al = al; pc.Bh = vt; pc.Bl = nullptr;
    pc.strideAz = (long long)NDIM*NDIM; pc.strideBz = DDIM*NDIM;
    pc.lda = 1024; pc.ldb = 1024; pc.K = 1024;
    pc.scale = 1.f; pc.outH = ch; pc.outL = cl;
    gemm_hmma<3,2><<<dim3(1, 8, HEADS), 256, SMEM2>>>(pc);

    // 7. out proj (2-product): A = ctx split, B = WoT single
    GP po{};
    po.Ah = ch; po.Al = cl; po.Bh = wot; po.Bl = nullptr;
    po.strideAz = 0; po.strideBz = 0;
    po.lda = 1024; po.ldb = 1024; po.K = 1024;
    po.scale = 1.f; po.bias = bo; po.outF = out;
    gemm_hmma<4,2><<<gProj, 256, SMEM2>>>(po);
}

// round 6
// speedup vs baseline: 2.5260x; 1.0539x over previous
#include <cuda_runtime.h>
#include <cuda_fp16.h>
#include <cstdint>

// ===========================================================================
// EntmaxAttention B=8, N=1024, C=1024, H=8, D=128, alpha=1.5
// out  = [8,1024,1024]   -> d_out[0..8388608)
// attn = [8,8,1024,1024] -> d_out[8388608..75497472)
//
// Base sm_103: GEMMs via mma.sync m16n8k16 fp16 (HMMA), fp32 accum.
// Scores chain (Q,K proj + scores): fp16 split x fp16 split, 3 products.
// V proj / out proj: A split x B single, 2 products. ctx: single x single.
// Pipelined fragment loads, 3-stage cp.async, 128x128 tiles, BK=32.
// ===========================================================================

#define BDIM 8
#define HDIM 8
#define NDIM 1024
#define CDIM 1024
#define DDIM 128
#define OUT_ELEMS (BDIM*NDIM*CDIM)
#define HEADS (BDIM*HDIM)

#define ROWB 80                   // padded row stride (bytes) = 40 halves
#define TILE_BYTES 10240          // 128 rows * 80B
#define NSTAGE 3

__device__ __forceinline__ uint32_t smem_u32(const void* p) {
    uint32_t a;
    asm("{ .reg .u64 t; cvta.to.shared.u64 t, %1; cvt.u32.u64 %0, t; }"
        : "=r"(a) : "l"(p));
    return a;
}
__device__ __forceinline__ void cpa16(uint32_t dst, const void* src) {
    asm volatile("cp.async.cg.shared.global [%0], [%1], 16;" :: "r"(dst), "l"(src));
}
__device__ __forceinline__ void cpa_commit() {
    asm volatile("cp.async.commit_group;" ::: "memory");
}
template<int N>
__device__ __forceinline__ void cpa_wait() {
    asm volatile("cp.async.wait_group %0;" :: "n"(N) : "memory");
}
__device__ __forceinline__ void mma16816(float* d, const uint32_t* a, const uint32_t* b) {
    asm volatile("mma.sync.aligned.m16n8k16.row.col.f32.f16.f16.f32 "
        "{%0,%1,%2,%3}, {%4,%5,%6,%7}, {%8,%9}, {%0,%1,%2,%3};"
        : "+f"(d[0]), "+f"(d[1]), "+f"(d[2]), "+f"(d[3])
        : "r"(a[0]), "r"(a[1]), "r"(a[2]), "r"(a[3]), "r"(b[0]), "r"(b[1]));
}
__device__ __forceinline__ void ldm_x4(uint32_t* r, uint32_t addr) {
    asm volatile("ldmatrix.sync.aligned.m8n8.x4.shared.b16 {%0,%1,%2,%3}, [%4];"
        : "=r"(r[0]), "=r"(r[1]), "=r"(r[2]), "=r"(r[3]) : "r"(addr));
}

// ------------------------- scratch (device globals) ------------------------
__device__ __half g_xh[OUT_ELEMS],  g_xl[OUT_ELEMS];
__device__ __half g_wqh[CDIM*CDIM], g_wql[CDIM*CDIM];
__device__ __half g_wkh[CDIM*CDIM], g_wkl[CDIM*CDIM];
__device__ __half g_wvt[CDIM*CDIM];
__device__ __half g_wot[CDIM*CDIM];
__device__ __half g_qh[OUT_ELEMS],  g_ql[OUT_ELEMS];      // [BH,N,D]
__device__ __half g_kh[OUT_ELEMS],  g_kl[OUT_ELEMS];      // [BH,N,D]
__device__ __half g_vt[OUT_ELEMS];                        // [BH,D,N]
__device__ __half g_ah[(size_t)HEADS*NDIM*NDIM];          // attn fp16
__device__ __half g_ch[OUT_ELEMS],  g_cl[OUT_ELEMS];      // ctx [B,N,C] split

// ------------------------- prep kernels -------------------------------------
__global__ void __launch_bounds__(256) split_kernel(
    const float* __restrict__ src, __half* __restrict__ hi,
    __half* __restrict__ lo, int n)
{
    int i = blockIdx.x * 256 + threadIdx.x;
    if (i < n) {
        float v = src[i];
        __half h = __float2half(v);
        hi[i] = h;
        lo[i] = __float2half(v - __half2float(h));
    }
}

__global__ void __launch_bounds__(1024) splitT2_kernel(
    const float* __restrict__ W0, const float* __restrict__ W1,
    __half* __restrict__ h0, __half* __restrict__ l0,
    __half* __restrict__ h1, __half* __restrict__ l1)
{
    const float* W = blockIdx.z ? W1 : W0;
    __half* hiT = blockIdx.z ? h1 : h0;
    __half* loT = blockIdx.z ? l1 : l0;
    __shared__ float t[32][33];
    int bx = blockIdx.x * 32, by = blockIdx.y * 32;
    int x = threadIdx.x, y = threadIdx.y;
    t[y][x] = W[(size_t)(by + y) * CDIM + bx + x];
    __syncthreads();
    float v = t[x][y];
    __half h = __float2half(v);
    size_t o = (size_t)(bx + y) * CDIM + by + x;
    hiT[o] = h;
    loT[o] = __float2half(v - __half2float(h));
}

__global__ void __launch_bounds__(1024) cvtT2_kernel(
    const float* __restrict__ W0, const float* __restrict__ W1,
    __half* __restrict__ t0, __half* __restrict__ t1)
{
    const float* W = blockIdx.z ? W1 : W0;
    __half* hT = blockIdx.z ? t1 : t0;
    __shared__ float t[32][33];
    int bx = blockIdx.x * 32, by = blockIdx.y * 32;
    int x = threadIdx.x, y = threadIdx.y;
    t[y][x] = W[(size_t)(by + y) * CDIM + bx + x];
    __syncthreads();
    hT[(size_t)(bx + y) * CDIM + by + x] = __float2half(t[x][y]);
}

// ------------------------- generic HMMA GEMM --------------------------------
// D[m,n] = sum_k A[m,k]*B[n,k]  (both K-major), 128x128 tile, BK=32.
// NPROD 3: A=Ah+Al, B=Bh+Bl -> AhBh+AhBl+AlBh   stage: Ah|Al|Bh|Bl
// NPROD 2: A=Ah+Al, B single -> AhB+AlB         stage: Ah|Al|B
// NPROD 1: A single, B single -> AB             stage: A|B
// MODE 0: QK proj -> hi/lo fp16 [B,H,N,D] (+bias)
// MODE 1: V proj  -> single fp16 vT [B,H,D,N] (+bias)
// MODE 2: scores  -> fp32*scale at outF[z<<20]
// MODE 3: ctx     -> hi/lo fp16 ctx [B,N,C]
// MODE 4: out proj-> fp32+bias at outF
struct GP {
    const __half *Ah, *Al, *Bh, *Bl;
    long long strideAz, strideBz;
    int lda, ldb, K;
    const float* bias;
    float scale;
    float* outF;
    __half *outH, *outL;
};

template<int MODE, int NPROD>
__global__ void __launch_bounds__(256, (NPROD <= 2) ? 2 : 1) gemm_hmma(GP p)
{
    constexpr int NT = (NPROD == 3) ? 4 : ((NPROD == 2) ? 3 : 2);
    constexpr uint32_t STAGE = NT * TILE_BYTES;
    constexpr uint32_t BOFF = (NPROD == 1) ? TILE_BYTES : 2u * TILE_BYTES;
    extern __shared__ char smem[];
    const uint32_t sbase = smem_u32(smem);
    const int tid = threadIdx.x;
    const int wid = tid >> 5;
    const int lane = tid & 31;
    const int g = lane >> 2;
    const int tq = lane & 3;
    const int warp_m = (wid >> 2) * 64;
    const int warp_n = (wid & 3) * 32;
    const int z = blockIdx.z;
    const int row0 = blockIdx.y * 128;
    const int col0 = blockIdx.x * 128;

    const __half* Ah = p.Ah + (size_t)z * p.strideAz;
    const __half* Al = (NPROD >= 2) ? (p.Al + (size_t)z * p.strideAz) : nullptr;
    const __half* Bh = p.Bh + (size_t)z * p.strideBz;
    const __half* Bl = (NPROD == 3) ? (p.Bl + (size_t)z * p.strideBz) : nullptr;

    float acc[4][4][4];
    #pragma unroll
    for (int i = 0; i < 4; i++)
        #pragma unroll
        for (int j = 0; j < 4; j++)
            #pragma unroll
            for (int e = 0; e < 4; e++) acc[i][j][e] = 0.f;

    const int nchunk = p.K >> 5;

    const uint32_t a_off = (uint32_t)((warp_m + (lane & 15)) * ROWB + (lane >> 4) * 16);
    const uint32_t b_off = (uint32_t)((warp_n + (lane & 7) + ((lane >> 4) << 3)) * ROWB
                                      + ((lane >> 3) & 1) * 16);

    auto prefetch = [&](int c) {
        int s = c % NSTAGE;
        int k0 = c << 5;
        uint32_t sb = sbase + s * STAGE;
        #pragma unroll
        for (int it = 0; it < 2; it++) {
            int id = tid + it * 256;
            int r = id >> 2;
            int ch = id & 3;
            uint32_t doff = (uint32_t)(r * ROWB + ch * 16);
            size_t ga = (size_t)(row0 + r) * p.lda + k0 + ch * 8;
            size_t gb = (size_t)(col0 + r) * p.ldb + k0 + ch * 8;
            cpa16(sb + doff, Ah + ga);
            if (NPROD >= 2) cpa16(sb + TILE_BYTES + doff, Al + ga);
            cpa16(sb + BOFF + doff, Bh + gb);
            if (NPROD == 3) cpa16(sb + BOFF + TILE_BYTES + doff, Bl + gb);
        }
        cpa_commit();
    };

    prefetch(0);
    if (nchunk > 1) prefetch(1);

    for (int c = 0; c < nchunk; c++) {
        if (c + 1 < nchunk) cpa_wait<1>(); else cpa_wait<0>();
        __syncthreads();
        if (c + 2 < nchunk) prefetch(c + 2);

        uint32_t stg = sbase + (uint32_t)((c % NSTAGE) * STAGE);

        // --- preload all B fragments for both k-steps ---
        uint32_t bhf[2][4][2];
        uint32_t blf[2][4][2];
        #pragma unroll
        for (int s16 = 0; s16 < 2; s16++) {
            #pragma unroll
            for (int jp = 0; jp < 2; jp++) {
                uint32_t ba = stg + BOFF + b_off + (uint32_t)(s16 * 32)
                            + (uint32_t)(jp * 16 * ROWB);
                uint32_t r4[4];
                ldm_x4(r4, ba);
                bhf[s16][jp*2][0] = r4[0]; bhf[s16][jp*2][1] = r4[1];
                bhf[s16][jp*2+1][0] = r4[2]; bhf[s16][jp*2+1][1] = r4[3];
                if (NPROD == 3) {
                    ldm_x4(r4, ba + TILE_BYTES);
                    blf[s16][jp*2][0] = r4[0]; blf[s16][jp*2][1] = r4[1];
                    blf[s16][jp*2+1][0] = r4[2]; blf[s16][jp*2+1][1] = r4[3];
                }
            }
        }

        // --- A fragments pipelined one i-tile ahead of the MMAs ---
        uint32_t ahf[2][2][4], alf[2][2][4];   // [buf][kstep][reg]
        #pragma unroll
        for (int s16 = 0; s16 < 2; s16++) {
            uint32_t aa = stg + a_off + (uint32_t)(s16 * 32);
            ldm_x4(ahf[0][s16], aa);
            if (NPROD >= 2) ldm_x4(alf[0][s16], aa + TILE_BYTES);
        }
        #pragma unroll
        for (int i = 0; i < 4; i++) {
            const int cur = i & 1, nxt = cur ^ 1;
            if (i < 3) {
                uint32_t aa = stg + a_off + (uint32_t)((i + 1) * 16 * ROWB);
                #pragma unroll
                for (int s16 = 0; s16 < 2; s16++) {
                    ldm_x4(ahf[nxt][s16], aa + (uint32_t)(s16 * 32));
                    if (NPROD >= 2) ldm_x4(alf[nxt][s16], aa + (uint32_t)(s16 * 32) + TILE_BYTES);
                }
            }
            #pragma unroll
            for (int s16 = 0; s16 < 2; s16++)
                #pragma unroll
                for (int j = 0; j < 4; j++) {
                    mma16816(acc[i][j], ahf[cur][s16], bhf[s16][j]);
                    if (NPROD == 3) mma16816(acc[i][j], ahf[cur][s16], blf[s16][j]);
                    if (NPROD >= 2) mma16816(acc[i][j], alf[cur][s16], bhf[s16][j]);
                }
        }
        // no trailing __syncthreads: top-of-loop barrier orders stage reuse
    }

    // --- epilogue ---
    #pragma unroll
    for (int i = 0; i < 4; i++) {
        #pragma unroll
        for (int j = 0; j < 4; j++) {
            #pragma unroll
            for (int e = 0; e < 4; e++) {
                int m  = row0 + warp_m + i*16 + g + ((e >> 1) ? 8 : 0);
                int cc = col0 + warp_n + j*8 + tq*2 + (e & 1);
                float val = acc[i][j][e];
                if (MODE == 0) {
                    float v = val + p.bias[cc];
                    int b = m >> 10, nn = m & 1023;
                    int h = cc >> 7, d = cc & 127;
                    size_t o = ((size_t)(((b*8 + h) << 10) + nn)) * 128 + d;
                    __half hh = __float2half(v);
                    p.outH[o] = hh;
                    p.outL[o] = __float2half(v - __half2float(hh));
                } else if (MODE == 1) {
                    float v = val + p.bias[cc];
                    int b = m >> 10, nn = m & 1023;
                    int h = cc >> 7, d = cc & 127;
                    size_t o = ((size_t)(((b*8 + h) << 7) + d)) * 1024 + nn;
                    p.outH[o] = __float2half(v);
                } else if (MODE == 2) {
                    p.outF[((size_t)z << 20) + (size_t)m * 1024 + cc] = val * p.scale;
                } else if (MODE == 3) {
                    int b = z >> 3, h = z & 7;
                    size_t o = ((size_t)((b << 10) + m)) * 1024 + h * 128 + cc;
                    __half hh = __float2half(val);
                    p.outH[o] = hh;
                    p.outL[o] = __float2half(val - __half2float(hh));
                } else {
                    p.outF[(size_t)m * 1024 + cc] = val + p.bias[cc];
                }
            }
        }
    }
}

// ------------------------- entmax (in place, + fp16 attn) ------------------
__global__ void __launch_bounds__(256) entmax_kernel(
    float* __restrict__ attn, __half* __restrict__ ah)
{
    int gwarp = (blockIdx.x * blockDim.x + threadIdx.x) >> 5;
    int lane  = threadIdx.x & 31;
    size_t rbase = (size_t)gwarp * 1024;
    float* row = attn + rbase;

    float xm[32];
    #pragma unroll
    for (int i = 0; i < 32; i++) xm[i] = 0.5f * row[i*32 + lane];

    float mx = xm[0];
    #pragma unroll
    for (int i = 1; i < 32; i++) mx = fmaxf(mx, xm[i]);
    #pragma unroll
    for (int o = 16; o > 0; o >>= 1)
        mx = fmaxf(mx, __shfl_xor_sync(0xffffffffu, mx, o));

    float tau_lo = mx - 1.0f;
    float dm = 1.0f - 0.03125f;

    float s = 0.f;
    #pragma unroll
    for (int i = 0; i < 32; i++) {
        float t = fmaxf(xm[i] - tau_lo, 0.f);
        s = fmaf(t, t, s);
    }
    #pragma unroll
    for (int o = 16; o > 0; o >>= 1)
        s += __shfl_xor_sync(0xffffffffu, s, o);
    float f_lo = s - 1.0f;

    float tau_m = tau_lo;
    #pragma unroll 1
    for (int it = 0; it < 34; it++) {
        dm *= 0.5f;
        tau_m = tau_lo + dm;
        float fs = 0.f;
        #pragma unroll
        for (int i = 0; i < 32; i++) {
            float t = fmaxf(xm[i] - tau_m, 0.f);
            fs = fmaf(t, t, fs);
        }
        #pragma unroll
        for (int o = 16; o > 0; o >>= 1)
            fs += __shfl_xor_sync(0xffffffffu, fs, o);
        if ((fs - 1.0f) * f_lo >= 0.f) tau_lo = tau_m;
    }

    float pv[32];
    float psum = 0.f;
    #pragma unroll
    for (int i = 0; i < 32; i++) {
        float t = fmaxf(xm[i] - tau_m, 0.f);
        pv[i] = t * t;
        psum += pv[i];
    }
    #pragma unroll
    for (int o = 16; o > 0; o >>= 1)
        psum += __shfl_xor_sync(0xffffffffu, psum, o);
    float inv = 1.0f / psum;
    #pragma unroll
    for (int i = 0; i < 32; i++) {
        float v = pv[i] * inv;
        int idx = i*32 + lane;
        row[idx] = v;
        ah[rbase + idx] = __float2half(v);
    }
}

// ---------------------------------------------------------------------------
extern "C" void kernel_launch(void* const* d_in, const int* in_sizes, int n_in,
                              void* d_out, int out_size)
{
    const float* x  = (const float*)d_in[0];
    const float* Wq = (const float*)d_in[1];
    const float* bq = (const float*)d_in[2];
    const float* Wk = (const float*)d_in[3];
    const float* bk = (const float*)d_in[4];
    const float* Wv = (const float*)d_in[5];
    const float* bv = (const float*)d_in[6];
    const float* Wo = (const float*)d_in[7];
    const float* bo = (const float*)d_in[8];

    float* out  = (float*)d_out;
    float* attn = out + OUT_ELEMS;

    const int SMEM3 = NSTAGE * 4 * TILE_BYTES;   // 122880
    const int SMEM2 = NSTAGE * 3 * TILE_BYTES;   //  92160
    const int SMEM1 = NSTAGE * 2 * TILE_BYTES;   //  61440
    cudaFuncSetAttribute((const void*)gemm_hmma<0,3>, cudaFuncAttributeMaxDynamicSharedMemorySize, SMEM3);
    cudaFuncSetAttribute((const void*)gemm_hmma<1,2>, cudaFuncAttributeMaxDynamicSharedMemorySize, SMEM2);
    cudaFuncSetAttribute((const void*)gemm_hmma<2,3>, cudaFuncAttributeMaxDynamicSharedMemorySize, SMEM3);
    cudaFuncSetAttribute((const void*)gemm_hmma<3,1>, cudaFuncAttributeMaxDynamicSharedMemorySize, SMEM1);
    cudaFuncSetAttribute((const void*)gemm_hmma<4,2>, cudaFuncAttributeMaxDynamicSharedMemorySize, SMEM2);

    __half *xh,*xl,*wqh,*wql,*wkh,*wkl,*wvt,*wot;
    __half *qh,*ql,*kh,*kl,*vt,*ah,*ch,*cl;
    cudaGetSymbolAddress((void**)&xh,  g_xh);  cudaGetSymbolAddress((void**)&xl,  g_xl);
    cudaGetSymbolAddress((void**)&wqh, g_wqh); cudaGetSymbolAddress((void**)&wql, g_wql);
    cudaGetSymbolAddress((void**)&wkh, g_wkh); cudaGetSymbolAddress((void**)&wkl, g_wkl);
    cudaGetSymbolAddress((void**)&wvt, g_wvt); cudaGetSymbolAddress((void**)&wot, g_wot);
    cudaGetSymbolAddress((void**)&qh,  g_qh);  cudaGetSymbolAddress((void**)&ql,  g_ql);
    cudaGetSymbolAddress((void**)&kh,  g_kh);  cudaGetSymbolAddress((void**)&kl,  g_kl);
    cudaGetSymbolAddress((void**)&vt,  g_vt);
    cudaGetSymbolAddress((void**)&ah,  g_ah);
    cudaGetSymbolAddress((void**)&ch,  g_ch);  cudaGetSymbolAddress((void**)&cl,  g_cl);

    // 1. prep
    split_kernel<<<OUT_ELEMS/256, 256>>>(x, xh, xl, OUT_ELEMS);
    dim3 tg(32, 32);
    splitT2_kernel<<<dim3(32,32,2), tg>>>(Wq, Wk, wqh, wql, wkh, wkl);
    cvtT2_kernel<<<dim3(32,32,2), tg>>>(Wv, Wo, wvt, wot);

    dim3 gProj(8, 64, 1);

    // 2. V proj (2-product)
    GP pv{};
    pv.Ah = xh; pv.Al = xl; pv.Bh = wvt;
    pv.strideAz = 0; pv.strideBz = 0;
    pv.lda = 1024; pv.ldb = 1024; pv.K = 1024;
    pv.bias = bv; pv.scale = 1.f; pv.outH = vt;
    gemm_hmma<1,2><<<gProj, 256, SMEM2>>>(pv);

    // 3. Q,K proj (3-product)
    GP p{};
    p.Ah = xh; p.Al = xl; p.lda = 1024; p.ldb = 1024; p.K = 1024;
    p.strideAz = 0; p.strideBz = 0; p.scale = 1.f;
    p.Bh = wqh; p.Bl = wql; p.bias = bq; p.outH = qh; p.outL = ql;
    gemm_hmma<0,3><<<gProj, 256, SMEM3>>>(p);
    p.Bh = wkh; p.Bl = wkl; p.bias = bk; p.outH = kh; p.outL = kl;
    gemm_hmma<0,3><<<gProj, 256, SMEM3>>>(p);

    // 4. scores (3-product), K=128
    GP ps{};
    ps.Ah = qh; ps.Al = ql; ps.Bh = kh; ps.Bl = kl;
    ps.strideAz = NDIM*DDIM; ps.strideBz = NDIM*DDIM;
    ps.lda = 128; ps.ldb = 128; ps.K = 128;
    ps.scale = 0.088388347648318440550f;
    ps.outF = attn;
    gemm_hmma<2,3><<<dim3(8, 8, HEADS), 256, SMEM3>>>(ps);

    // 5. entmax (in place) + single fp16 split
    entmax_kernel<<<8192, 256>>>(attn, ah);

    // 6. ctx (1-product): A = attn fp16, B = vT, K=1024
    GP pc{};
    pc.Ah = ah; pc.Bh = vt;
    pc.strideAz = (long long)NDIM*NDIM; pc.strideBz = DDIM*NDIM;
    pc.lda = 1024; pc.ldb = 1024; pc.K = 1024;
    pc.scale = 1.f; pc.outH = ch; pc.outL = cl;
    gemm_hmma<3,1><<<dim3(1, 8, HEADS), 256, SMEM1>>>(pc);

    // 7. out proj (2-product)
    GP po{};
    po.Ah = ch; po.Al = cl; po.Bh = wot;
    po.strideAz = 0; po.strideBz = 0;
    po.lda = 1024; po.ldb = 1024; po.K = 1024;
    po.scale = 1.f; po.bias = bo; po.outF = out;
    gemm_hmma<4,2><<<gProj, 256, SMEM2>>>(po);
}